// round 9
// baseline (speedup 1.0000x reference)
#include <cuda_runtime.h>
#include <math.h>

#define R_HASH 0.2f
#define EPSF   1e-12f
#define BATCH  4096

typedef unsigned long long u64;

// scratch (device globals: sanctioned scratch mechanism)
__device__ float g_h1[BATCH * 16 * 16 * 16];
__device__ float g_h2[BATCH * 20 * 8 * 8];
__device__ float g_h3[BATCH * 20 * 4 * 4];
__device__ int   g_qh[3 * BATCH];
__device__ int   g_kh[96];
__device__ float g_aux[48];
__device__ int   g_ord1[1 + 2 * 2049];
__device__ int   g_ord2[1 + 2 * 2050];
__device__ int   g_ord3[1 + 2 * 2050];
// duplicated-pair weight tables: per (filter,cin) channel 60 floats:
// 5 rows x 12 floats; row r, pos p: p<10 -> W[f*25 + r*5 + p/2] (dup pair), else 0
__device__ __align__(16) float g_w1d[48 * 60];
__device__ __align__(16) float g_w2d[320 * 60];
__device__ __align__(16) float g_w3d[400 * 60];

// ---------------------------------------------------------------------------
__device__ __forceinline__ void ffma2(u64& d, u64 a, u64 b)
{
    asm("fma.rn.f32x2 %0, %1, %2, %0;" : "+l"(d) : "l"(a), "l"(b));
}
__device__ __forceinline__ void unpack2(u64 v, float& lo, float& hi)
{
    asm("mov.b64 {%0, %1}, %2;" : "=f"(lo), "=f"(hi) : "l"(v));
}

// ---------------------------------------------------------------------------
// Build dup-pair weight tables for all 3 layers
// ---------------------------------------------------------------------------
__global__ void prep_wd(const float* __restrict__ W1,
                        const float* __restrict__ W2,
                        const float* __restrict__ W3)
{
    int t = blockIdx.x * blockDim.x + threadIdx.x;
    int stride = gridDim.x * blockDim.x;
    for (int i = t; i < 48 * 60; i += stride) {
        int f = i / 60, r = (i % 60) / 12, p = i % 12;
        g_w1d[i] = (p < 10) ? W1[f * 25 + r * 5 + (p >> 1)] : 0.f;
    }
    for (int i = t; i < 320 * 60; i += stride) {
        int f = i / 60, r = (i % 60) / 12, p = i % 12;
        g_w2d[i] = (p < 10) ? W2[f * 25 + r * 5 + (p >> 1)] : 0.f;
    }
    for (int i = t; i < 400 * 60; i += stride) {
        int f = i / 60, r = (i % 60) / 12, p = i % 12;
        g_w3d[i] = (p < 10) ? W3[f * 25 + r * 5 + (p >> 1)] : 0.f;
    }
}

// ---------------------------------------------------------------------------
// Filter hashes (one warp per layer)
// ---------------------------------------------------------------------------
__device__ __forceinline__ void kh_layer(const float* W, const float* a,
                                         const float* c, int Cout, int d,
                                         int* kh_out, int t)
{
    float nrm = 0.f;
    if (t < Cout) {
        for (int j = 0; j < d; j++) { float v = W[t * d + j]; nrm += v * v; }
        nrm = sqrtf(nrm);
    }
    float mx = nrm;
    #pragma unroll
    for (int off = 16; off; off >>= 1)
        mx = fmaxf(mx, __shfl_xor_sync(0xffffffffu, mx, off));
    float scale = 1.f / (mx + EPSF);
    if (t < Cout) {
        float dot = 0.f, ss = 0.f;
        for (int j = 0; j < d; j++) {
            float v = W[t * d + j] * scale;
            dot += v * a[j];
            ss  += v * v;
        }
        float n = sqrtf(ss);
        float p = n;
        #pragma unroll
        for (int m = 0; m < 5; m++) { p = p * p; dot += p * a[d + m]; }
        dot += c[0];
        long long f = (long long)floorf(dot / R_HASH);
        kh_out[t] = (int)(((f % 2) + 2) % 2);
    }
}

__global__ void kh_kernel(const float* W1, const float* a1, const float* c1,
                          const float* W2, const float* a2, const float* c2,
                          const float* W3, const float* a3, const float* c3)
{
    int warp = threadIdx.x >> 5, t = threadIdx.x & 31;
    if (warp == 0) kh_layer(W1, a1, c1, 16, 3 * 25,  g_kh + 0,  t);
    if (warp == 1) kh_layer(W2, a2, c2, 20, 16 * 25, g_kh + 32, t);
    if (warp == 2) kh_layer(W3, a3, c3, 20, 20 * 25, g_kh + 64, t);
    if (warp == 3 && t < 16) {
        float s = 0.f; for (int j = 0; j < 25; j++) s += a2[t * 25 + j];
        g_aux[t] = s;
    }
    if (warp == 4 && t < 20) {
        float s = 0.f; for (int j = 0; j < 25; j++) s += a3[t * 25 + j];
        g_aux[16 + t] = s;
    }
    if (warp == 5) {
        if (t < 3) {
            float s = 0.f; for (int j = 0; j < 25; j++) s += a1[t * 25 + j];
            g_aux[38 + t] = s;
        }
        if (t == 3) { float s = 0.f; for (int m = 0; m < 5; m++) s += a2[400 + m]; g_aux[36] = s; }
        if (t == 4) { float s = 0.f; for (int m = 0; m < 5; m++) s += a3[500 + m]; g_aux[37] = s; }
        if (t == 5) { float s = 0.f; for (int m = 0; m < 5; m++) s += a1[75 + m];  g_aux[41] = s; }
    }
}

// ---------------------------------------------------------------------------
// Layer-1 query hash: one warp per sample
// ---------------------------------------------------------------------------
__global__ __launch_bounds__(256)
void qh1_kernel(const float* __restrict__ x, const float* __restrict__ c1,
                int* __restrict__ qh_out)
{
    int warp = threadIdx.x >> 5, lane = threadIdx.x & 31;
    int b = blockIdx.x * 8 + warp;
    const float4* xb = (const float4*)(x + (size_t)b * 3072);
    float s[3];
    #pragma unroll
    for (int c = 0; c < 3; c++) {
        float p = 0.f;
        #pragma unroll
        for (int i = lane; i < 256; i += 32) {
            float4 v = xb[c * 256 + i];
            p += (v.x + v.y) + (v.z + v.w);
        }
        #pragma unroll
        for (int off = 16; off; off >>= 1)
            p += __shfl_xor_sync(0xffffffffu, p, off);
        s[c] = p;
    }
    if (lane == 0) {
        float dot = 0.f, ss = 0.f;
        #pragma unroll
        for (int c = 0; c < 3; c++) {
            float cm = s[c] * (1.f / 1024.f);
            dot += cm * g_aux[38 + c];
            ss  += cm * cm;
        }
        float v = dot / (sqrtf(25.f * ss) + EPSF) + 0.5f * g_aux[41] + c1[0];
        long long f = (long long)floorf(v / R_HASH);
        qh_out[b] = (int)(((f % 2) + 2) % 2);
    }
}

// ---------------------------------------------------------------------------
// Pair samples by hash class (stable partition -> pairs within each class).
// NC = 2 (class = qa[s]) or 4 (class = qa[s]*2 + qb[s]).
// ord[0] = npairs; ord[1+2p], ord[2+2p] = sample pair (s1==s0 marks dup).
// ---------------------------------------------------------------------------
template <int NC>
__global__ void pair_kernel(const int* __restrict__ qa,
                            const int* __restrict__ qb,
                            int* __restrict__ ord)
{
    __shared__ int sorted[BATCH];
    __shared__ int cnts[128 * NC];
    __shared__ int base[NC], cnt[NC], pb[NC + 1];
    int t = threadIdx.x;  // 128 threads, 32 samples each
    int loc[NC];
    #pragma unroll
    for (int c = 0; c < NC; c++) loc[c] = 0;
    for (int i = 0; i < 32; i++) {
        int s = t * 32 + i;
        int c = (NC == 2) ? qa[s] : (qa[s] * 2 + qb[s]);
        loc[c]++;
    }
    #pragma unroll
    for (int c = 0; c < NC; c++) cnts[c * 128 + t] = loc[c];
    __syncthreads();
    if (t == 0) {
        int run = 0;
        for (int c = 0; c < NC; c++) {
            base[c] = run;
            for (int i = 0; i < 128; i++) {
                int v = cnts[c * 128 + i];
                cnts[c * 128 + i] = run;
                run += v;
            }
            cnt[c] = run - base[c];
        }
        int np = 0;
        for (int c = 0; c < NC; c++) { pb[c] = np; np += (cnt[c] + 1) >> 1; }
        pb[NC] = np;
        ord[0] = np;
    }
    __syncthreads();
    #pragma unroll
    for (int c = 0; c < NC; c++) loc[c] = cnts[c * 128 + t];
    for (int i = 0; i < 32; i++) {
        int s = t * 32 + i;
        int c = (NC == 2) ? qa[s] : (qa[s] * 2 + qb[s]);
        sorted[loc[c]++] = s;
    }
    __syncthreads();
    int np = pb[NC];
    for (int p = t; p < np; p += 128) {
        int c = 0;
        #pragma unroll
        for (int cc = 1; cc < NC; cc++) if (p >= pb[cc]) c = cc;
        int q = p - pb[c];
        int s0 = sorted[base[c] + 2 * q];
        int s1 = (2 * q + 1 < cnt[c]) ? sorted[base[c] + 2 * q + 1] : s0;
        ord[1 + 2 * p] = s0;
        ord[2 + 2 * p] = s1;
    }
}

// ---------------------------------------------------------------------------
// Paired conv5x5(pad2)+bias+relu+mask+maxpool2 using packed f32x2 FMAs.
// One block = one sample PAIR with identical masks. x tile sample-interleaved
// in smem (LDS.128 yields ready x-pairs); weights dup-paired in gmem.
// ---------------------------------------------------------------------------
template <int CIN, int COUT, int H, int W, int WPAD, int T, int MINB, bool EPI>
__global__ __launch_bounds__(T, MINB)
void conv_pair(const float* __restrict__ in, float* __restrict__ out,
               const float* __restrict__ wd, const float* __restrict__ bias,
               const int* __restrict__ kh, const int* __restrict__ qh,
               const int* __restrict__ kh_prev, const int* __restrict__ qh_prev,
               const int* __restrict__ ord,
               const float* __restrict__ asum_next,
               const float* __restrict__ tail_next,
               const float* __restrict__ c_next, int* __restrict__ qh_next)
{
    constexpr int HP = H + 4;
    constexpr int PH = H / 2, PW = W / 2, PX2 = PW / 2;
    constexpr int PP = PH * PX2;
    constexpr int SEG = (PP < 32) ? PP : 32;
    constexpr int CHW = HP * WPAD;

    if (blockIdx.x >= (unsigned)__ldg(ord)) return;

    extern __shared__ float sm[];
    float* sx  = sm;                          // CIN*CHW*2 (interleaved pairs)
    float* scm = sx + CIN * CHW * 2;          // 2*COUT
    int* ish   = (int*)(scm + 2 * COUT);      // [0]=nact,[1]=nci
    int* actco = ish + 2;                     // COUT
    int* actci = actco + COUT;                // CIN

    const int t  = threadIdx.x;
    const int s0 = __ldg(ord + 1 + 2 * blockIdx.x);
    const int s1 = __ldg(ord + 2 + 2 * blockIdx.x);
    const bool dup = (s0 == s1);

    if (t == 0) {
        int n = 0, qv = qh[s0];
        for (int co = 0; co < COUT; co++)
            if (kh[co] == qv) actco[n++] = co;
        ish[0] = n;
    } else if (t == 32) {
        int n = 0;
        if (kh_prev) {
            int qv = qh_prev[s0];
            for (int c = 0; c < CIN; c++)
                if (kh_prev[c] == qv) actci[n++] = c;
        } else {
            for (int c = 0; c < CIN; c++) actci[n++] = c;
        }
        ish[1] = n;
    }
    if (EPI) for (int i = t; i < 2 * COUT; i += T) scm[i] = 0.f;
    __syncthreads();
    const int n_ci = ish[1];
    const int total = ish[0] * PP;

    // stage interleaved tile: sx[(j*CHW+pos)*2 + {0,1}] = x_{s0,s1}
    for (int i = t; i < n_ci * CHW; i += T) {
        int j = i / CHW, pos = i % CHW;
        int c = actci[j];
        int py = pos / WPAD, px = pos % WPAD;
        int y = py - 2, x = px - 2;
        float v0 = 0.f, v1 = 0.f;
        if ((unsigned)y < (unsigned)H && (unsigned)x < (unsigned)W) {
            int off = y * W + x;
            v0 = in[((size_t)s0 * CIN + c) * (H * W) + off];
            v1 = in[((size_t)s1 * CIN + c) * (H * W) + off];
        }
        *(float2*)(sx + 2 * i) = make_float2(v0, v1);
    }
    __syncthreads();

    for (int item = t;; item += T) {
        if (!__ballot_sync(0xffffffffu, item < total)) break;
        float val0 = 0.f, val1 = 0.f;
        int co = 0;
        if (item < total) {
            co = actco[item / PP];
            int rr = item % PP;
            int py = rr / PX2, px2 = rr % PX2;

            u64 acc2[2][4] = {};
            const float* xb = sx + ((2 * py) * WPAD + 4 * px2) * 2;
            const float* wf = wd + (size_t)co * CIN * 60;

            for (int j = 0; j < n_ci; j++) {
                const float* wc = wf + actci[j] * 60;
                const float* xs = xb + j * CHW * 2;
                u64 prev[5];
                #pragma unroll
                for (int rw = 0; rw < 6; rw++) {
                    const ulonglong2* xp = (const ulonglong2*)(xs + rw * WPAD * 2);
                    ulonglong2 xa = xp[0], xb2 = xp[1], xc = xp[2], xd = xp[3];
                    u64 xq[8] = {xa.x, xa.y, xb2.x, xb2.y, xc.x, xc.y, xd.x, xd.y};
                    u64 cur[5];
                    if (rw < 5) {
                        const ulonglong2* wr = (const ulonglong2*)(wc + rw * 12);
                        ulonglong2 q0 = __ldg(wr + 0), q1 = __ldg(wr + 1), q2 = __ldg(wr + 2);
                        cur[0] = q0.x; cur[1] = q0.y; cur[2] = q1.x;
                        cur[3] = q1.y; cur[4] = q2.x;
                        #pragma unroll
                        for (int kx = 0; kx < 5; kx++) {
                            ffma2(acc2[0][0], xq[kx + 0], cur[kx]);
                            ffma2(acc2[0][1], xq[kx + 1], cur[kx]);
                            ffma2(acc2[0][2], xq[kx + 2], cur[kx]);
                            ffma2(acc2[0][3], xq[kx + 3], cur[kx]);
                        }
                    }
                    if (rw > 0) {
                        #pragma unroll
                        for (int kx = 0; kx < 5; kx++) {
                            ffma2(acc2[1][0], xq[kx + 0], prev[kx]);
                            ffma2(acc2[1][1], xq[kx + 1], prev[kx]);
                            ffma2(acc2[1][2], xq[kx + 2], prev[kx]);
                            ffma2(acc2[1][3], xq[kx + 3], prev[kx]);
                        }
                    }
                    if (rw < 5) {
                        #pragma unroll
                        for (int k = 0; k < 5; k++) prev[k] = cur[k];
                    }
                }
            }
            float a[2][4][2];
            #pragma unroll
            for (int r = 0; r < 2; r++)
                #pragma unroll
                for (int q = 0; q < 4; q++)
                    unpack2(acc2[r][q], a[r][q][0], a[r][q][1]);
            float bv = __ldg(bias + co);
            // sample 0
            {
                float v00 = fmaxf(a[0][0][0] + bv, 0.f), v01 = fmaxf(a[0][1][0] + bv, 0.f);
                float v02 = fmaxf(a[0][2][0] + bv, 0.f), v03 = fmaxf(a[0][3][0] + bv, 0.f);
                float v10 = fmaxf(a[1][0][0] + bv, 0.f), v11 = fmaxf(a[1][1][0] + bv, 0.f);
                float v12 = fmaxf(a[1][2][0] + bv, 0.f), v13 = fmaxf(a[1][3][0] + bv, 0.f);
                float o0 = fmaxf(fmaxf(v00, v01), fmaxf(v10, v11));
                float o1 = fmaxf(fmaxf(v02, v03), fmaxf(v12, v13));
                *(float2*)&out[(((size_t)s0 * COUT + co) * PH + py) * PW + 2 * px2] =
                    make_float2(o0, o1);
                val0 = o0 + o1;
            }
            // sample 1
            {
                float v00 = fmaxf(a[0][0][1] + bv, 0.f), v01 = fmaxf(a[0][1][1] + bv, 0.f);
                float v02 = fmaxf(a[0][2][1] + bv, 0.f), v03 = fmaxf(a[0][3][1] + bv, 0.f);
                float v10 = fmaxf(a[1][0][1] + bv, 0.f), v11 = fmaxf(a[1][1][1] + bv, 0.f);
                float v12 = fmaxf(a[1][2][1] + bv, 0.f), v13 = fmaxf(a[1][3][1] + bv, 0.f);
                float o0 = fmaxf(fmaxf(v00, v01), fmaxf(v10, v11));
                float o1 = fmaxf(fmaxf(v02, v03), fmaxf(v12, v13));
                if (!dup)
                    *(float2*)&out[(((size_t)s1 * COUT + co) * PH + py) * PW + 2 * px2] =
                        make_float2(o0, o1);
                val1 = o0 + o1;
            }
        }
        if (EPI) {
            #pragma unroll
            for (int off = SEG / 2; off; off >>= 1) {
                val0 += __shfl_xor_sync(0xffffffffu, val0, off);
                val1 += __shfl_xor_sync(0xffffffffu, val1, off);
            }
            if ((t & (SEG - 1)) == 0 && item < total) {
                atomicAdd(&scm[co], val0);
                atomicAdd(&scm[COUT + co], val1);
            }
        }
    }

    if (EPI) {
        __syncthreads();
        if (t < 2) {
            if (t == 1 && dup) return;
            int s = t ? s1 : s0;
            float dot = 0.f, ssum = 0.f;
            const float inv = 1.f / (float)(PH * PW);
            for (int c = 0; c < COUT; c++) {
                float cm = scm[t * COUT + c] * inv;
                dot  += cm * asum_next[c];
                ssum += cm * cm;
            }
            float v = dot / (sqrtf(25.f * ssum) + EPSF) + 0.5f * tail_next[0] + c_next[0];
            long long f = (long long)floorf(v / R_HASH);
            qh_next[s] = (int)(((f % 2) + 2) % 2);
        }
    }
}

// ---------------------------------------------------------------------------
// FC with layer-3 mask applied on load
// ---------------------------------------------------------------------------
__global__ __launch_bounds__(256)
void fc_kernel(const float* __restrict__ h, const float* __restrict__ Wo,
               const float* __restrict__ bo, float* __restrict__ out,
               const int* __restrict__ kh3, const int* __restrict__ qh3)
{
    __shared__ float sW[3200];
    __shared__ float sb[10];
    __shared__ int skh[20];
    int t = threadIdx.x;
    for (int i = t; i < 3200; i += 256) sW[i] = Wo[i];
    if (t < 10) sb[t] = bo[t];
    if (t < 20) skh[t] = kh3[t];
    __syncthreads();
    int warp = t / 32, lane = t % 32;
    int b = blockIdx.x * 8 + warp;
    int qv = qh3[b];
    const float* hb = h + (size_t)b * 320;
    float x[10];
    #pragma unroll
    for (int j = 0; j < 10; j++) {
        int idx = lane + j * 32;
        x[j] = (skh[idx >> 4] == qv) ? hb[idx] : 0.f;
    }
    #pragma unroll
    for (int o = 0; o < 10; o++) {
        float p = 0.f;
        #pragma unroll
        for (int j = 0; j < 10; j++) p += x[j] * sW[o * 320 + lane + j * 32];
        #pragma unroll
        for (int off = 16; off; off >>= 1) p += __shfl_xor_sync(0xffffffffu, p, off);
        if (lane == 0) out[b * 10 + o] = p + sb[o];
    }
}

// ---------------------------------------------------------------------------
static inline int smem_bytes(int CIN, int COUT, int HP, int WPAD)
{
    return 4 * (CIN * HP * WPAD * 2 + 2 * COUT + 2 + COUT + CIN);
}

extern "C" void kernel_launch(void* const* d_in, const int* in_sizes, int n_in,
                              void* d_out, int out_size)
{
    const float* x  = (const float*)d_in[0];
    const float* W1 = (const float*)d_in[1];
    const float* b1 = (const float*)d_in[2];
    const float* a1 = (const float*)d_in[3];
    const float* c1 = (const float*)d_in[4];
    const float* W2 = (const float*)d_in[5];
    const float* b2 = (const float*)d_in[6];
    const float* a2 = (const float*)d_in[7];
    const float* c2 = (const float*)d_in[8];
    const float* W3 = (const float*)d_in[9];
    const float* b3 = (const float*)d_in[10];
    const float* a3 = (const float*)d_in[11];
    const float* c3 = (const float*)d_in[12];
    const float* Wo = (const float*)d_in[13];
    const float* bo = (const float*)d_in[14];
    float* out = (float*)d_out;

    float *h1, *h2, *h3, *aux, *w1d, *w2d, *w3d;
    int *qh, *kh, *ord1, *ord2, *ord3;
    cudaGetSymbolAddress((void**)&h1, g_h1);
    cudaGetSymbolAddress((void**)&h2, g_h2);
    cudaGetSymbolAddress((void**)&h3, g_h3);
    cudaGetSymbolAddress((void**)&qh, g_qh);
    cudaGetSymbolAddress((void**)&kh, g_kh);
    cudaGetSymbolAddress((void**)&aux, g_aux);
    cudaGetSymbolAddress((void**)&w1d, g_w1d);
    cudaGetSymbolAddress((void**)&w2d, g_w2d);
    cudaGetSymbolAddress((void**)&w3d, g_w3d);
    cudaGetSymbolAddress((void**)&ord1, g_ord1);
    cudaGetSymbolAddress((void**)&ord2, g_ord2);
    cudaGetSymbolAddress((void**)&ord3, g_ord3);

    const int sm1 = smem_bytes(3, 16, 36, 36);
    const int sm2 = smem_bytes(16, 20, 20, 24);
    const int sm3 = smem_bytes(20, 20, 12, 12);

    cudaFuncSetAttribute((const void*)conv_pair<3, 16, 32, 32, 36, 128, 4, true>,
                         cudaFuncAttributeMaxDynamicSharedMemorySize, sm1);
    cudaFuncSetAttribute((const void*)conv_pair<16, 20, 16, 16, 24, 128, 3, true>,
                         cudaFuncAttributeMaxDynamicSharedMemorySize, sm2);
    cudaFuncSetAttribute((const void*)conv_pair<20, 20, 8, 8, 12, 64, 8, false>,
                         cudaFuncAttributeMaxDynamicSharedMemorySize, sm3);

    prep_wd<<<60, 256>>>(W1, W2, W3);
    kh_kernel<<<1, 192>>>(W1, a1, c1, W2, a2, c2, W3, a3, c3);
    qh1_kernel<<<BATCH / 8, 256>>>(x, c1, qh);

    pair_kernel<2><<<1, 128>>>(qh, nullptr, ord1);
    conv_pair<3, 16, 32, 32, 36, 128, 4, true><<<2049, 128, sm1>>>(
        x, h1, w1d, b1, kh, qh, nullptr, nullptr, ord1,
        aux + 0, aux + 36, c2, qh + BATCH);

    pair_kernel<4><<<1, 128>>>(qh, qh + BATCH, ord2);
    conv_pair<16, 20, 16, 16, 24, 128, 3, true><<<2050, 128, sm2>>>(
        h1, h2, w2d, b2, kh + 32, qh + BATCH, kh, qh, ord2,
        aux + 16, aux + 37, c3, qh + 2 * BATCH);

    pair_kernel<4><<<1, 128>>>(qh + BATCH, qh + 2 * BATCH, ord3);
    conv_pair<20, 20, 8, 8, 12, 64, 8, false><<<2050, 64, sm3>>>(
        h2, h3, w3d, b3, kh + 64, qh + 2 * BATCH, kh + 32, qh + BATCH, ord3,
        nullptr, nullptr, nullptr, nullptr);

    fc_kernel<<<BATCH / 8, 256>>>(h3, Wo, bo, out, kh + 64, qh + 2 * BATCH);
}

// round 11
// speedup vs baseline: 1.3296x; 1.3296x over previous
#include <cuda_runtime.h>
#include <math.h>

#define R_HASH 0.2f
#define EPSF   1e-12f
#define BATCH  4096

// scratch (device globals: sanctioned scratch mechanism)
__device__ float g_h1[BATCH * 16 * 16 * 16];
__device__ float g_h2[BATCH * 20 * 8 * 8];
__device__ float g_h3[BATCH * 20 * 4 * 4];
__device__ int   g_qh[3 * BATCH];
__device__ int   g_kh[96];
__device__ float g_aux[48];
__device__ __align__(16) float g_w1p[48 * 28];   // padded weights, stride 28
__device__ __align__(16) float g_w2p[320 * 28];
__device__ __align__(16) float g_w3p[400 * 28];

// ---------------------------------------------------------------------------
// Fused setup kernel: blocks 0-2 = filter hashes (one warp per filter,
// lane-parallel dot products); blocks 3-7 = weight padding + aux sums.
// ---------------------------------------------------------------------------
__global__ void kh_all(const float* __restrict__ W1, const float* __restrict__ a1,
                       const float* __restrict__ c1,
                       const float* __restrict__ W2, const float* __restrict__ a2,
                       const float* __restrict__ c2,
                       const float* __restrict__ W3, const float* __restrict__ a3,
                       const float* __restrict__ c3)
{
    const int blk = blockIdx.x;
    if (blk < 3) {
        const float* W = (blk == 0) ? W1 : (blk == 1) ? W2 : W3;
        const float* a = (blk == 0) ? a1 : (blk == 1) ? a2 : a3;
        const float* c = (blk == 0) ? c1 : (blk == 1) ? c2 : c3;
        const int Cout = (blk == 0) ? 16 : 20;
        const int d    = (blk == 0) ? 75 : (blk == 1) ? 400 : 500;
        int* khp = g_kh + blk * 32;

        __shared__ float norms[32];
        __shared__ float smx;
        int w = threadIdx.x >> 5, lane = threadIdx.x & 31;

        for (int f = w; f < Cout; f += 8) {
            float s = 0.f;
            for (int j = lane; j < d; j += 32) { float v = W[f * d + j]; s += v * v; }
            #pragma unroll
            for (int off = 16; off; off >>= 1)
                s += __shfl_xor_sync(0xffffffffu, s, off);
            if (lane == 0) norms[f] = sqrtf(s);
        }
        __syncthreads();
        if (threadIdx.x < 32) {
            float v = (lane < Cout) ? norms[lane] : 0.f;
            #pragma unroll
            for (int off = 16; off; off >>= 1)
                v = fmaxf(v, __shfl_xor_sync(0xffffffffu, v, off));
            if (lane == 0) smx = v;
        }
        __syncthreads();
        const float scale = 1.f / (smx + EPSF);
        for (int f = w; f < Cout; f += 8) {
            float dot = 0.f, ss = 0.f;
            for (int j = lane; j < d; j += 32) {
                float v = W[f * d + j] * scale;
                dot += v * a[j];
                ss  += v * v;
            }
            #pragma unroll
            for (int off = 16; off; off >>= 1) {
                dot += __shfl_xor_sync(0xffffffffu, dot, off);
                ss  += __shfl_xor_sync(0xffffffffu, ss, off);
            }
            if (lane == 0) {
                float n = sqrtf(ss), p = n;
                #pragma unroll
                for (int m = 0; m < 5; m++) { p = p * p; dot += p * a[d + m]; }
                dot += c[0];
                long long fl = (long long)floorf(dot / R_HASH);
                khp[f] = (int)(((fl % 2) + 2) % 2);
            }
        }
    } else {
        const int t = threadIdx.x;
        if (blk == 3) {
            if (t < 16) {
                float s = 0.f; for (int j = 0; j < 25; j++) s += a2[t * 25 + j];
                g_aux[t] = s;
            } else if (t >= 32 && t < 52) {
                int r = t - 32;
                float s = 0.f; for (int j = 0; j < 25; j++) s += a3[r * 25 + j];
                g_aux[16 + r] = s;
            } else if (t >= 64 && t < 67) {
                int r = t - 64;
                float s = 0.f; for (int j = 0; j < 25; j++) s += a1[r * 25 + j];
                g_aux[38 + r] = s;
            } else if (t == 67) {
                float s = 0.f; for (int m = 0; m < 5; m++) s += a2[400 + m];
                g_aux[36] = s;
            } else if (t == 68) {
                float s = 0.f; for (int m = 0; m < 5; m++) s += a3[500 + m];
                g_aux[37] = s;
            } else if (t == 69) {
                float s = 0.f; for (int m = 0; m < 5; m++) s += a1[75 + m];
                g_aux[41] = s;
            }
        }
        const int base = (blk - 3) * 256 + t;
        const int stride = 5 * 256;
        for (int i = base; i < 48 * 28; i += stride) {
            int f = i / 28, k = i % 28;
            g_w1p[i] = (k < 25) ? W1[f * 25 + k] : 0.f;
        }
        for (int i = base; i < 320 * 28; i += stride) {
            int f = i / 28, k = i % 28;
            g_w2p[i] = (k < 25) ? W2[f * 25 + k] : 0.f;
        }
        for (int i = base; i < 400 * 28; i += stride) {
            int f = i / 28, k = i % 28;
            g_w3p[i] = (k < 25) ? W3[f * 25 + k] : 0.f;
        }
    }
}

// ---------------------------------------------------------------------------
// Layer-1 query hash: one warp per sample
// ---------------------------------------------------------------------------
__global__ __launch_bounds__(256)
void qh1_kernel(const float* __restrict__ x, const float* __restrict__ c1,
                int* __restrict__ qh_out)
{
    int warp = threadIdx.x >> 5, lane = threadIdx.x & 31;
    int b = blockIdx.x * 8 + warp;
    const float4* xb = (const float4*)(x + (size_t)b * 3072);
    float s[3];
    #pragma unroll
    for (int c = 0; c < 3; c++) {
        float p = 0.f;
        #pragma unroll
        for (int i = lane; i < 256; i += 32) {
            float4 v = xb[c * 256 + i];
            p += (v.x + v.y) + (v.z + v.w);
        }
        #pragma unroll
        for (int off = 16; off; off >>= 1)
            p += __shfl_xor_sync(0xffffffffu, p, off);
        s[c] = p;
    }
    if (lane == 0) {
        float dot = 0.f, ss = 0.f;
        #pragma unroll
        for (int c = 0; c < 3; c++) {
            float cm = s[c] * (1.f / 1024.f);
            dot += cm * g_aux[38 + c];
            ss  += cm * cm;
        }
        float v = dot / (sqrtf(25.f * ss) + EPSF) + 0.5f * g_aux[41] + c1[0];
        long long f = (long long)floorf(v / R_HASH);
        qh_out[b] = (int)(((f % 2) + 2) % 2);
    }
}

// ---------------------------------------------------------------------------
// Fused conv5x5(pad2)+bias+relu+mask+maxpool2 (R7 mainloop, unchanged).
// Compacted active-channel x tiles in smem; padded weights via 7x float4 __ldg.
// ---------------------------------------------------------------------------
template <int CIN, int COUT, int H, int W, int WPAD, int SPB, int T, int MINB, bool EPI>
__global__ __launch_bounds__(T, MINB)
void conv_fused(const float* __restrict__ in, float* __restrict__ out,
                const float* __restrict__ wpad, const float* __restrict__ bias,
                const int* __restrict__ kh, const int* __restrict__ qh,
                const int* __restrict__ kh_prev, const int* __restrict__ qh_prev,
                const float* __restrict__ asum_next,
                const float* __restrict__ tail_next,
                const float* __restrict__ c_next, int* __restrict__ qh_next)
{
    constexpr int HP = H + 4;
    constexpr int PH = H / 2, PW = W / 2, PX2 = PW / 2;
    constexpr int PP = PH * PX2;
    constexpr int SEG = (PP < 32) ? PP : 32;
    constexpr int CHW = HP * WPAD;

    extern __shared__ float sm[];
    float* sx  = sm;
    float* scm = sx + SPB * CIN * CHW;
    int* nact  = (int*)(scm + SPB * COUT);
    int* soff  = nact + SPB;
    int* actco = soff + SPB + 1;
    int* nci   = actco + SPB * COUT;
    int* actci = nci + SPB;
    int* sxoff = actci + SPB * CIN;

    const int b0 = blockIdx.x * SPB;
    const int t  = threadIdx.x;

    if (t < SPB) {
        int s = t, n = 0, qv = qh[b0 + s];
        for (int co = 0; co < COUT; co++)
            if (kh[co] == qv) actco[s * COUT + n++] = co;
        nact[s] = n;
    } else if (t >= 32 && t < 32 + SPB) {
        int s = t - 32, n = 0;
        if (kh_prev) {
            int qv = qh_prev[b0 + s];
            for (int c = 0; c < CIN; c++)
                if (kh_prev[c] == qv) actci[s * CIN + n++] = c;
        } else {
            for (int c = 0; c < CIN; c++) actci[s * CIN + n++] = c;
        }
        nci[s] = n;
    }
    if (EPI) for (int i = t; i < SPB * COUT; i += T) scm[i] = 0.f;
    __syncthreads();
    if (t == 0) {
        int o = 0, xo = 0;
        for (int s = 0; s < SPB; s++) {
            soff[s] = o;  o  += nact[s] * PP;
            sxoff[s] = xo; xo += nci[s];
        }
        soff[SPB] = o; sxoff[SPB] = xo;
    }
    __syncthreads();

    const int total_ch = sxoff[SPB];
    for (int i = t; i < total_ch * CHW; i += T) {
        int pos = i % CHW, ch = i / CHW;
        int s = 0;
        #pragma unroll
        for (int ss = 0; ss < SPB - 1; ss++)
            if (ch >= sxoff[ss + 1]) s = ss + 1;
        int c = actci[s * CIN + (ch - sxoff[s])];
        int py = pos / WPAD, px = pos % WPAD;
        int y = py - 2, x = px - 2;
        float v = 0.f;
        if ((unsigned)y < (unsigned)H && (unsigned)x < (unsigned)W)
            v = in[((size_t)(b0 + s) * CIN + c) * (H * W) + y * W + x];
        sx[i] = v;
    }
    __syncthreads();
    const int total = soff[SPB];

    for (int item = t;; item += T) {
        if (!__ballot_sync(0xffffffffu, item < total)) break;
        float val = 0.f;
        int s = 0, co = 0;
        if (item < total) {
            #pragma unroll
            for (int ss = 0; ss < SPB - 1; ss++)
                if (item >= soff[ss + 1]) s = ss + 1;
            int local = item - soff[s];
            co = actco[s * COUT + local / PP];
            int rr = local % PP;
            int py = rr / PX2, px2 = rr % PX2;

            float acc[2][4] = {};
            const float* xb = sx + (size_t)sxoff[s] * CHW + (2 * py) * WPAD + 4 * px2;
            const int n_ci = nci[s];
            const int* ci = actci + s * CIN;
            const float* wb_ = wpad + (size_t)co * CIN * 28;

            for (int j = 0; j < n_ci; j++) {
                const float4* wr = (const float4*)(wb_ + ci[j] * 28);
                float4 q0 = __ldg(wr + 0), q1 = __ldg(wr + 1), q2 = __ldg(wr + 2);
                float4 q3 = __ldg(wr + 3), q4 = __ldg(wr + 4), q5 = __ldg(wr + 5);
                float4 q6 = __ldg(wr + 6);
                float w[25] = {q0.x, q0.y, q0.z, q0.w, q1.x, q1.y, q1.z, q1.w,
                               q2.x, q2.y, q2.z, q2.w, q3.x, q3.y, q3.z, q3.w,
                               q4.x, q4.y, q4.z, q4.w, q5.x, q5.y, q5.z, q5.w,
                               q6.x};
                const float* xs = xb + j * CHW;
                #pragma unroll
                for (int rw = 0; rw < 6; rw++) {
                    float4 x0 = *(const float4*)(xs + rw * WPAD);
                    float4 x1 = *(const float4*)(xs + rw * WPAD + 4);
                    float xr[8] = {x0.x, x0.y, x0.z, x0.w, x1.x, x1.y, x1.z, x1.w};
                    if (rw < 5) {
                        #pragma unroll
                        for (int kx = 0; kx < 5; kx++) {
                            float wa = w[rw * 5 + kx];
                            acc[0][0] += xr[kx + 0] * wa;
                            acc[0][1] += xr[kx + 1] * wa;
                            acc[0][2] += xr[kx + 2] * wa;
                            acc[0][3] += xr[kx + 3] * wa;
                        }
                    }
                    if (rw > 0) {
                        #pragma unroll
                        for (int kx = 0; kx < 5; kx++) {
                            float wb = w[(rw - 1) * 5 + kx];
                            acc[1][0] += xr[kx + 0] * wb;
                            acc[1][1] += xr[kx + 1] * wb;
                            acc[1][2] += xr[kx + 2] * wb;
                            acc[1][3] += xr[kx + 3] * wb;
                        }
                    }
                }
            }
            float bv = __ldg(bias + co);
            float v00 = fmaxf(acc[0][0] + bv, 0.f), v01 = fmaxf(acc[0][1] + bv, 0.f);
            float v02 = fmaxf(acc[0][2] + bv, 0.f), v03 = fmaxf(acc[0][3] + bv, 0.f);
            float v10 = fmaxf(acc[1][0] + bv, 0.f), v11 = fmaxf(acc[1][1] + bv, 0.f);
            float v12 = fmaxf(acc[1][2] + bv, 0.f), v13 = fmaxf(acc[1][3] + bv, 0.f);
            float o0 = fmaxf(fmaxf(v00, v01), fmaxf(v10, v11));
            float o1 = fmaxf(fmaxf(v02, v03), fmaxf(v12, v13));
            float2* op = (float2*)&out[(((size_t)(b0 + s) * COUT + co) * PH + py) * PW + px2 * 2];
            *op = make_float2(o0, o1);
            val = o0 + o1;
        }
        if (EPI) {
            #pragma unroll
            for (int off = SEG / 2; off; off >>= 1)
                val += __shfl_xor_sync(0xffffffffu, val, off);
            if ((t & (SEG - 1)) == 0 && item < total)
                atomicAdd(&scm[s * COUT + co], val);
        }
    }

    if (EPI) {
        __syncthreads();
        if (t < SPB) {
            int s = t;
            float dot = 0.f, ssum = 0.f;
            const float inv = 1.f / (float)(PH * PW);
            for (int c = 0; c < COUT; c++) {
                float cm = scm[s * COUT + c] * inv;
                dot  += cm * asum_next[c];
                ssum += cm * cm;
            }
            float v = dot / (sqrtf(25.f * ssum) + EPSF) + 0.5f * tail_next[0] + c_next[0];
            long long f = (long long)floorf(v / R_HASH);
            qh_next[b0 + s] = (int)(((f % 2) + 2) % 2);
        }
    }
}

// ---------------------------------------------------------------------------
// FC with layer-3 mask applied on load
// ---------------------------------------------------------------------------
__global__ __launch_bounds__(256)
void fc_kernel(const float* __restrict__ h, const float* __restrict__ Wo,
               const float* __restrict__ bo, float* __restrict__ out,
               const int* __restrict__ kh3, const int* __restrict__ qh3)
{
    __shared__ float sW[3200];
    __shared__ float sb[10];
    __shared__ int skh[20];
    int t = threadIdx.x;
    for (int i = t; i < 3200; i += 256) sW[i] = Wo[i];
    if (t < 10) sb[t] = bo[t];
    if (t < 20) skh[t] = kh3[t];
    __syncthreads();
    int warp = t / 32, lane = t % 32;
    int b = blockIdx.x * 8 + warp;
    int qv = qh3[b];
    const float* hb = h + (size_t)b * 320;
    float x[10];
    #pragma unroll
    for (int j = 0; j < 10; j++) {
        int idx = lane + j * 32;
        x[j] = (skh[idx >> 4] == qv) ? hb[idx] : 0.f;
    }
    #pragma unroll
    for (int o = 0; o < 10; o++) {
        float p = 0.f;
        #pragma unroll
        for (int j = 0; j < 10; j++) p += x[j] * sW[o * 320 + lane + j * 32];
        #pragma unroll
        for (int off = 16; off; off >>= 1) p += __shfl_xor_sync(0xffffffffu, p, off);
        if (lane == 0) out[b * 10 + o] = p + sb[o];
    }
}

// ---------------------------------------------------------------------------
static inline int smem_bytes(int CIN, int COUT, int SPB, int HP, int WPAD)
{
    int fl = SPB * CIN * HP * WPAD + SPB * COUT;
    int it = SPB + (SPB + 1) + SPB * COUT + SPB + SPB * CIN + (SPB + 1);
    return 4 * (fl + it);
}

extern "C" void kernel_launch(void* const* d_in, const int* in_sizes, int n_in,
                              void* d_out, int out_size)
{
    const float* x  = (const float*)d_in[0];
    const float* W1 = (const float*)d_in[1];
    const float* b1 = (const float*)d_in[2];
    const float* a1 = (const float*)d_in[3];
    const float* c1 = (const float*)d_in[4];
    const float* W2 = (const float*)d_in[5];
    const float* b2 = (const float*)d_in[6];
    const float* a2 = (const float*)d_in[7];
    const float* c2 = (const float*)d_in[8];
    const float* W3 = (const float*)d_in[9];
    const float* b3 = (const float*)d_in[10];
    const float* a3 = (const float*)d_in[11];
    const float* c3 = (const float*)d_in[12];
    const float* Wo = (const float*)d_in[13];
    const float* bo = (const float*)d_in[14];
    float* out = (float*)d_out;

    float *h1, *h2, *h3, *aux, *w1p, *w2p, *w3p; int *qh, *kh;
    cudaGetSymbolAddress((void**)&h1, g_h1);
    cudaGetSymbolAddress((void**)&h2, g_h2);
    cudaGetSymbolAddress((void**)&h3, g_h3);
    cudaGetSymbolAddress((void**)&qh, g_qh);
    cudaGetSymbolAddress((void**)&kh, g_kh);
    cudaGetSymbolAddress((void**)&aux, g_aux);
    cudaGetSymbolAddress((void**)&w1p, g_w1p);
    cudaGetSymbolAddress((void**)&w2p, g_w2p);
    cudaGetSymbolAddress((void**)&w3p, g_w3p);

    const int sm1 = smem_bytes(3, 16, 1, 36, 36);
    const int sm2 = smem_bytes(16, 20, 2, 20, 24);
    const int sm3 = smem_bytes(20, 20, 2, 12, 12);

    cudaFuncSetAttribute((const void*)conv_fused<3, 16, 32, 32, 36, 1, 256, 4, true>,
                         cudaFuncAttributeMaxDynamicSharedMemorySize, sm1);
    cudaFuncSetAttribute((const void*)conv_fused<16, 20, 16, 16, 24, 2, 256, 4, true>,
                         cudaFuncAttributeMaxDynamicSharedMemorySize, sm2);
    cudaFuncSetAttribute((const void*)conv_fused<20, 20, 8, 8, 12, 2, 128, 8, false>,
                         cudaFuncAttributeMaxDynamicSharedMemorySize, sm3);

    kh_all<<<8, 256>>>(W1, a1, c1, W2, a2, c2, W3, a3, c3);
    qh1_kernel<<<BATCH / 8, 256>>>(x, c1, qh);

    conv_fused<3, 16, 32, 32, 36, 1, 256, 4, true><<<BATCH, 256, sm1>>>(
        x, h1, w1p, b1, kh, qh, nullptr, nullptr,
        aux + 0, aux + 36, c2, qh + BATCH);

    conv_fused<16, 20, 16, 16, 24, 2, 256, 4, true><<<BATCH / 2, 256, sm2>>>(
        h1, h2, w2p, b2, kh + 32, qh + BATCH, kh, qh,
        aux + 16, aux + 37, c3, qh + 2 * BATCH);

    conv_fused<20, 20, 8, 8, 12, 2, 128, 8, false><<<BATCH / 2, 128, sm3>>>(
        h2, h3, w3p, b3, kh + 64, qh + 2 * BATCH, kh + 32, qh + BATCH,
        nullptr, nullptr, nullptr, nullptr);

    fc_kernel<<<BATCH / 8, 256>>>(h3, Wo, bo, out, kh + 64, qh + 2 * BATCH);
}

// round 12
// speedup vs baseline: 1.3781x; 1.0365x over previous
#include <cuda_runtime.h>
#include <math.h>

#define R_HASH 0.2f
#define EPSF   1e-12f
#define BATCH  4096

// scratch (device globals: sanctioned scratch mechanism)
__device__ float g_h1[BATCH * 16 * 16 * 16];
__device__ float g_h2[BATCH * 20 * 8 * 8];
__device__ float g_h3[BATCH * 20 * 4 * 4];
__device__ int   g_qh[3 * BATCH];
__device__ int   g_kh[96];
__device__ float g_aux[48];
__device__ __align__(16) float g_w1p[48 * 28];   // padded weights, stride 28
__device__ __align__(16) float g_w2p[320 * 28];
__device__ __align__(16) float g_w3p[400 * 28];

// ---------------------------------------------------------------------------
// Fused setup kernel: blocks 0-2 = filter hashes (one warp per filter,
// lane-parallel dot products); blocks 3-7 = weight padding + aux sums.
// ---------------------------------------------------------------------------
__global__ void kh_all(const float* __restrict__ W1, const float* __restrict__ a1,
                       const float* __restrict__ c1,
                       const float* __restrict__ W2, const float* __restrict__ a2,
                       const float* __restrict__ c2,
                       const float* __restrict__ W3, const float* __restrict__ a3,
                       const float* __restrict__ c3)
{
    const int blk = blockIdx.x;
    if (blk < 3) {
        const float* W = (blk == 0) ? W1 : (blk == 1) ? W2 : W3;
        const float* a = (blk == 0) ? a1 : (blk == 1) ? a2 : a3;
        const float* c = (blk == 0) ? c1 : (blk == 1) ? c2 : c3;
        const int Cout = (blk == 0) ? 16 : 20;
        const int d    = (blk == 0) ? 75 : (blk == 1) ? 400 : 500;
        int* khp = g_kh + blk * 32;

        __shared__ float norms[32];
        __shared__ float smx;
        int w = threadIdx.x >> 5, lane = threadIdx.x & 31;

        for (int f = w; f < Cout; f += 8) {
            float s = 0.f;
            for (int j = lane; j < d; j += 32) { float v = W[f * d + j]; s += v * v; }
            #pragma unroll
            for (int off = 16; off; off >>= 1)
                s += __shfl_xor_sync(0xffffffffu, s, off);
            if (lane == 0) norms[f] = sqrtf(s);
        }
        __syncthreads();
        if (threadIdx.x < 32) {
            float v = (lane < Cout) ? norms[lane] : 0.f;
            #pragma unroll
            for (int off = 16; off; off >>= 1)
                v = fmaxf(v, __shfl_xor_sync(0xffffffffu, v, off));
            if (lane == 0) smx = v;
        }
        __syncthreads();
        const float scale = 1.f / (smx + EPSF);
        for (int f = w; f < Cout; f += 8) {
            float dot = 0.f, ss = 0.f;
            for (int j = lane; j < d; j += 32) {
                float v = W[f * d + j] * scale;
                dot += v * a[j];
                ss  += v * v;
            }
            #pragma unroll
            for (int off = 16; off; off >>= 1) {
                dot += __shfl_xor_sync(0xffffffffu, dot, off);
                ss  += __shfl_xor_sync(0xffffffffu, ss, off);
            }
            if (lane == 0) {
                float n = sqrtf(ss), p = n;
                #pragma unroll
                for (int m = 0; m < 5; m++) { p = p * p; dot += p * a[d + m]; }
                dot += c[0];
                long long fl = (long long)floorf(dot / R_HASH);
                khp[f] = (int)(((fl % 2) + 2) % 2);
            }
        }
    } else {
        const int t = threadIdx.x;
        if (blk == 3) {
            if (t < 16) {
                float s = 0.f; for (int j = 0; j < 25; j++) s += a2[t * 25 + j];
                g_aux[t] = s;
            } else if (t >= 32 && t < 52) {
                int r = t - 32;
                float s = 0.f; for (int j = 0; j < 25; j++) s += a3[r * 25 + j];
                g_aux[16 + r] = s;
            } else if (t >= 64 && t < 67) {
                int r = t - 64;
                float s = 0.f; for (int j = 0; j < 25; j++) s += a1[r * 25 + j];
                g_aux[38 + r] = s;
            } else if (t == 67) {
                float s = 0.f; for (int m = 0; m < 5; m++) s += a2[400 + m];
                g_aux[36] = s;
            } else if (t == 68) {
                float s = 0.f; for (int m = 0; m < 5; m++) s += a3[500 + m];
                g_aux[37] = s;
            } else if (t == 69) {
                float s = 0.f; for (int m = 0; m < 5; m++) s += a1[75 + m];
                g_aux[41] = s;
            }
        }
        const int base = (blk - 3) * 256 + t;
        const int stride = 5 * 256;
        for (int i = base; i < 48 * 28; i += stride) {
            int f = i / 28, k = i % 28;
            g_w1p[i] = (k < 25) ? W1[f * 25 + k] : 0.f;
        }
        for (int i = base; i < 320 * 28; i += stride) {
            int f = i / 28, k = i % 28;
            g_w2p[i] = (k < 25) ? W2[f * 25 + k] : 0.f;
        }
        for (int i = base; i < 400 * 28; i += stride) {
            int f = i / 28, k = i % 28;
            g_w3p[i] = (k < 25) ? W3[f * 25 + k] : 0.f;
        }
    }
}

// ---------------------------------------------------------------------------
// Layer-1 query hash: one warp per sample
// ---------------------------------------------------------------------------
__global__ __launch_bounds__(256)
void qh1_kernel(const float* __restrict__ x, const float* __restrict__ c1,
                int* __restrict__ qh_out)
{
    int warp = threadIdx.x >> 5, lane = threadIdx.x & 31;
    int b = blockIdx.x * 8 + warp;
    const float4* xb = (const float4*)(x + (size_t)b * 3072);
    float s[3];
    #pragma unroll
    for (int c = 0; c < 3; c++) {
        float p = 0.f;
        #pragma unroll
        for (int i = lane; i < 256; i += 32) {
            float4 v = xb[c * 256 + i];
            p += (v.x + v.y) + (v.z + v.w);
        }
        #pragma unroll
        for (int off = 16; off; off >>= 1)
            p += __shfl_xor_sync(0xffffffffu, p, off);
        s[c] = p;
    }
    if (lane == 0) {
        float dot = 0.f, ss = 0.f;
        #pragma unroll
        for (int c = 0; c < 3; c++) {
            float cm = s[c] * (1.f / 1024.f);
            dot += cm * g_aux[38 + c];
            ss  += cm * cm;
        }
        float v = dot / (sqrtf(25.f * ss) + EPSF) + 0.5f * g_aux[41] + c1[0];
        long long f = (long long)floorf(v / R_HASH);
        qh_out[b] = (int)(((f % 2) + 2) % 2);
    }
}

// ---------------------------------------------------------------------------
// Fused conv5x5(pad2)+bias+relu+mask+maxpool2 (R7/R11 mainloop).
// Compacted active-channel x tiles in smem; padded weights via 7x float4 __ldg.
// NOPREV=true specializes n_ci==CIN (identity channel map, no indirection).
// ---------------------------------------------------------------------------
template <int CIN, int COUT, int H, int W, int WPAD, int SPB, int T, int MINB,
          bool EPI, bool NOPREV>
__global__ __launch_bounds__(T, MINB)
void conv_fused(const float* __restrict__ in, float* __restrict__ out,
                const float* __restrict__ wpad, const float* __restrict__ bias,
                const int* __restrict__ kh, const int* __restrict__ qh,
                const int* __restrict__ kh_prev, const int* __restrict__ qh_prev,
                const float* __restrict__ asum_next,
                const float* __restrict__ tail_next,
                const float* __restrict__ c_next, int* __restrict__ qh_next)
{
    constexpr int HP = H + 4;
    constexpr int PH = H / 2, PW = W / 2, PX2 = PW / 2;
    constexpr int PP = PH * PX2;
    constexpr int SEG = (PP < 32) ? PP : 32;
    constexpr int CHW = HP * WPAD;

    extern __shared__ float sm[];
    float* sx  = sm;
    float* scm = sx + SPB * CIN * CHW;
    int* nact  = (int*)(scm + SPB * COUT);
    int* soff  = nact + SPB;
    int* actco = soff + SPB + 1;
    int* nci   = actco + SPB * COUT;
    int* actci = nci + SPB;
    int* sxoff = actci + SPB * CIN;

    const int b0 = blockIdx.x * SPB;
    const int t  = threadIdx.x;

    if (t < SPB) {
        int s = t, n = 0, qv = qh[b0 + s];
        for (int co = 0; co < COUT; co++)
            if (kh[co] == qv) actco[s * COUT + n++] = co;
        nact[s] = n;
    } else if (t >= 32 && t < 32 + SPB) {
        int s = t - 32, n = 0;
        if (!NOPREV) {
            int qv = qh_prev[b0 + s];
            for (int c = 0; c < CIN; c++)
                if (kh_prev[c] == qv) actci[s * CIN + n++] = c;
        } else {
            for (int c = 0; c < CIN; c++) actci[s * CIN + n++] = c;
        }
        nci[s] = n;
    }
    if (EPI) for (int i = t; i < SPB * COUT; i += T) scm[i] = 0.f;
    __syncthreads();
    if (t == 0) {
        int o = 0, xo = 0;
        for (int s = 0; s < SPB; s++) {
            soff[s] = o;  o  += nact[s] * PP;
            sxoff[s] = xo; xo += NOPREV ? CIN : nci[s];
        }
        soff[SPB] = o; sxoff[SPB] = xo;
    }
    __syncthreads();

    const int total_ch = sxoff[SPB];
    for (int i = t; i < total_ch * CHW; i += T) {
        int pos = i % CHW, ch = i / CHW;
        int s = 0;
        #pragma unroll
        for (int ss = 0; ss < SPB - 1; ss++)
            if (ch >= sxoff[ss + 1]) s = ss + 1;
        int c = NOPREV ? (ch - sxoff[s]) : actci[s * CIN + (ch - sxoff[s])];
        int py = pos / WPAD, px = pos % WPAD;
        int y = py - 2, x = px - 2;
        float v = 0.f;
        if ((unsigned)y < (unsigned)H && (unsigned)x < (unsigned)W)
            v = in[((size_t)(b0 + s) * CIN + c) * (H * W) + y * W + x];
        sx[i] = v;
    }
    __syncthreads();
    const int total = soff[SPB];

    for (int item = t;; item += T) {
        if (!__ballot_sync(0xffffffffu, item < total)) break;
        float val = 0.f;
        int s = 0, co = 0;
        if (item < total) {
            #pragma unroll
            for (int ss = 0; ss < SPB - 1; ss++)
                if (item >= soff[ss + 1]) s = ss + 1;
            int local = item - soff[s];
            co = actco[s * COUT + local / PP];
            int rr = local % PP;
            int py = rr / PX2, px2 = rr % PX2;

            float acc[2][4] = {};
            const float* xb = sx + (size_t)sxoff[s] * CHW + (2 * py) * WPAD + 4 * px2;
            const int n_ci = NOPREV ? CIN : nci[s];
            const int* ci = actci + s * CIN;
            const float* wb_ = wpad + (size_t)co * CIN * 28;

            for (int j = 0; j < n_ci; j++) {
                int c = NOPREV ? j : ci[j];
                const float4* wr = (const float4*)(wb_ + c * 28);
                float4 q0 = __ldg(wr + 0), q1 = __ldg(wr + 1), q2 = __ldg(wr + 2);
                float4 q3 = __ldg(wr + 3), q4 = __ldg(wr + 4), q5 = __ldg(wr + 5);
                float4 q6 = __ldg(wr + 6);
                float w[25] = {q0.x, q0.y, q0.z, q0.w, q1.x, q1.y, q1.z, q1.w,
                               q2.x, q2.y, q2.z, q2.w, q3.x, q3.y, q3.z, q3.w,
                               q4.x, q4.y, q4.z, q4.w, q5.x, q5.y, q5.z, q5.w,
                               q6.x};
                const float* xs = xb + j * CHW;
                #pragma unroll
                for (int rw = 0; rw < 6; rw++) {
                    float4 x0 = *(const float4*)(xs + rw * WPAD);
                    float4 x1 = *(const float4*)(xs + rw * WPAD + 4);
                    float xr[8] = {x0.x, x0.y, x0.z, x0.w, x1.x, x1.y, x1.z, x1.w};
                    if (rw < 5) {
                        #pragma unroll
                        for (int kx = 0; kx < 5; kx++) {
                            float wa = w[rw * 5 + kx];
                            acc[0][0] += xr[kx + 0] * wa;
                            acc[0][1] += xr[kx + 1] * wa;
                            acc[0][2] += xr[kx + 2] * wa;
                            acc[0][3] += xr[kx + 3] * wa;
                        }
                    }
                    if (rw > 0) {
                        #pragma unroll
                        for (int kx = 0; kx < 5; kx++) {
                            float wb = w[(rw - 1) * 5 + kx];
                            acc[1][0] += xr[kx + 0] * wb;
                            acc[1][1] += xr[kx + 1] * wb;
                            acc[1][2] += xr[kx + 2] * wb;
                            acc[1][3] += xr[kx + 3] * wb;
                        }
                    }
                }
            }
            float bv = __ldg(bias + co);
            float v00 = fmaxf(acc[0][0] + bv, 0.f), v01 = fmaxf(acc[0][1] + bv, 0.f);
            float v02 = fmaxf(acc[0][2] + bv, 0.f), v03 = fmaxf(acc[0][3] + bv, 0.f);
            float v10 = fmaxf(acc[1][0] + bv, 0.f), v11 = fmaxf(acc[1][1] + bv, 0.f);
            float v12 = fmaxf(acc[1][2] + bv, 0.f), v13 = fmaxf(acc[1][3] + bv, 0.f);
            float o0 = fmaxf(fmaxf(v00, v01), fmaxf(v10, v11));
            float o1 = fmaxf(fmaxf(v02, v03), fmaxf(v12, v13));
            float2* op = (float2*)&out[(((size_t)(b0 + s) * COUT + co) * PH + py) * PW + px2 * 2];
            *op = make_float2(o0, o1);
            val = o0 + o1;
        }
        if (EPI) {
            #pragma unroll
            for (int off = SEG / 2; off; off >>= 1)
                val += __shfl_xor_sync(0xffffffffu, val, off);
            if ((t & (SEG - 1)) == 0 && item < total)
                atomicAdd(&scm[s * COUT + co], val);
        }
    }

    if (EPI) {
        __syncthreads();
        if (t < SPB) {
            int s = t;
            float dot = 0.f, ssum = 0.f;
            const float inv = 1.f / (float)(PH * PW);
            for (int c = 0; c < COUT; c++) {
                float cm = scm[s * COUT + c] * inv;
                dot  += cm * asum_next[c];
                ssum += cm * cm;
            }
            float v = dot / (sqrtf(25.f * ssum) + EPSF) + 0.5f * tail_next[0] + c_next[0];
            long long f = (long long)floorf(v / R_HASH);
            qh_next[b0 + s] = (int)(((f % 2) + 2) % 2);
        }
    }
}

// ---------------------------------------------------------------------------
// FC with layer-3 mask applied on load
// ---------------------------------------------------------------------------
__global__ __launch_bounds__(256)
void fc_kernel(const float* __restrict__ h, const float* __restrict__ Wo,
               const float* __restrict__ bo, float* __restrict__ out,
               const int* __restrict__ kh3, const int* __restrict__ qh3)
{
    __shared__ float sW[3200];
    __shared__ float sb[10];
    __shared__ int skh[20];
    int t = threadIdx.x;
    for (int i = t; i < 3200; i += 256) sW[i] = Wo[i];
    if (t < 10) sb[t] = bo[t];
    if (t < 20) skh[t] = kh3[t];
    __syncthreads();
    int warp = t / 32, lane = t % 32;
    int b = blockIdx.x * 8 + warp;
    int qv = qh3[b];
    const float* hb = h + (size_t)b * 320;
    float x[10];
    #pragma unroll
    for (int j = 0; j < 10; j++) {
        int idx = lane + j * 32;
        x[j] = (skh[idx >> 4] == qv) ? hb[idx] : 0.f;
    }
    #pragma unroll
    for (int o = 0; o < 10; o++) {
        float p = 0.f;
        #pragma unroll
        for (int j = 0; j < 10; j++) p += x[j] * sW[o * 320 + lane + j * 32];
        #pragma unroll
        for (int off = 16; off; off >>= 1) p += __shfl_xor_sync(0xffffffffu, p, off);
        if (lane == 0) out[b * 10 + o] = p + sb[o];
    }
}

// ---------------------------------------------------------------------------
static inline int smem_bytes(int CIN, int COUT, int SPB, int HP, int WPAD)
{
    int fl = SPB * CIN * HP * WPAD + SPB * COUT;
    int it = SPB + (SPB + 1) + SPB * COUT + SPB + SPB * CIN + (SPB + 1);
    return 4 * (fl + it);
}

extern "C" void kernel_launch(void* const* d_in, const int* in_sizes, int n_in,
                              void* d_out, int out_size)
{
    const float* x  = (const float*)d_in[0];
    const float* W1 = (const float*)d_in[1];
    const float* b1 = (const float*)d_in[2];
    const float* a1 = (const float*)d_in[3];
    const float* c1 = (const float*)d_in[4];
    const float* W2 = (const float*)d_in[5];
    const float* b2 = (const float*)d_in[6];
    const float* a2 = (const float*)d_in[7];
    const float* c2 = (const float*)d_in[8];
    const float* W3 = (const float*)d_in[9];
    const float* b3 = (const float*)d_in[10];
    const float* a3 = (const float*)d_in[11];
    const float* c3 = (const float*)d_in[12];
    const float* Wo = (const float*)d_in[13];
    const float* bo = (const float*)d_in[14];
    float* out = (float*)d_out;

    float *h1, *h2, *h3, *aux, *w1p, *w2p, *w3p; int *qh, *kh;
    cudaGetSymbolAddress((void**)&h1, g_h1);
    cudaGetSymbolAddress((void**)&h2, g_h2);
    cudaGetSymbolAddress((void**)&h3, g_h3);
    cudaGetSymbolAddress((void**)&qh, g_qh);
    cudaGetSymbolAddress((void**)&kh, g_kh);
    cudaGetSymbolAddress((void**)&aux, g_aux);
    cudaGetSymbolAddress((void**)&w1p, g_w1p);
    cudaGetSymbolAddress((void**)&w2p, g_w2p);
    cudaGetSymbolAddress((void**)&w3p, g_w3p);

    const int sm1 = smem_bytes(3, 16, 1, 36, 36);
    const int sm2 = smem_bytes(16, 20, 1, 20, 24);
    const int sm3 = smem_bytes(20, 20, 2, 12, 12);

    cudaFuncSetAttribute((const void*)conv_fused<3, 16, 32, 32, 36, 1, 256, 4, true, true>,
                         cudaFuncAttributeMaxDynamicSharedMemorySize, sm1);
    cudaFuncSetAttribute((const void*)conv_fused<16, 20, 16, 16, 24, 1, 128, 7, true, false>,
                         cudaFuncAttributeMaxDynamicSharedMemorySize, sm2);
    cudaFuncSetAttribute((const void*)conv_fused<20, 20, 8, 8, 12, 2, 128, 8, false, false>,
                         cudaFuncAttributeMaxDynamicSharedMemorySize, sm3);

    kh_all<<<8, 256>>>(W1, a1, c1, W2, a2, c2, W3, a3, c3);
    qh1_kernel<<<BATCH / 8, 256>>>(x, c1, qh);

    conv_fused<3, 16, 32, 32, 36, 1, 256, 4, true, true><<<BATCH, 256, sm1>>>(
        x, h1, w1p, b1, kh, qh, nullptr, nullptr,
        aux + 0, aux + 36, c2, qh + BATCH);

    conv_fused<16, 20, 16, 16, 24, 1, 128, 7, true, false><<<BATCH, 128, sm2>>>(
        h1, h2, w2p, b2, kh + 32, qh + BATCH, kh, qh,
        aux + 16, aux + 37, c3, qh + 2 * BATCH);

    conv_fused<20, 20, 8, 8, 12, 2, 128, 8, false, false><<<BATCH / 2, 128, sm3>>>(
        h2, h3, w3p, b3, kh + 64, qh + 2 * BATCH, kh + 32, qh + BATCH,
        nullptr, nullptr, nullptr, nullptr);

    fc_kernel<<<BATCH / 8, 256>>>(h3, Wo, bo, out, kh + 64, qh + 2 * BATCH);
}

// round 13
// speedup vs baseline: 1.3867x; 1.0062x over previous
#include <cuda_runtime.h>
#include <math.h>

#define R_HASH 0.2f
#define EPSF   1e-12f
#define BATCH  4096

// scratch (device globals: sanctioned scratch mechanism)
__device__ float g_h1[BATCH * 16 * 16 * 16];
__device__ float g_h2[BATCH * 20 * 8 * 8];
__device__ float g_h3[BATCH * 20 * 4 * 4];
__device__ int   g_qh[3 * BATCH];
__device__ int   g_kh[96];
__device__ float g_aux[48];
__device__ __align__(16) float g_w1p[48 * 28];   // padded weights, stride 28
__device__ __align__(16) float g_w2p[320 * 28];
__device__ __align__(16) float g_w3p[400 * 28];

// ---------------------------------------------------------------------------
// Fused setup kernel: blocks 0-2 = filter hashes (one warp per filter,
// lane-parallel dot products); blocks 3-7 = weight padding + aux sums.
// ---------------------------------------------------------------------------
__global__ void kh_all(const float* __restrict__ W1, const float* __restrict__ a1,
                       const float* __restrict__ c1,
                       const float* __restrict__ W2, const float* __restrict__ a2,
                       const float* __restrict__ c2,
                       const float* __restrict__ W3, const float* __restrict__ a3,
                       const float* __restrict__ c3)
{
    const int blk = blockIdx.x;
    if (blk < 3) {
        const float* W = (blk == 0) ? W1 : (blk == 1) ? W2 : W3;
        const float* a = (blk == 0) ? a1 : (blk == 1) ? a2 : a3;
        const float* c = (blk == 0) ? c1 : (blk == 1) ? c2 : c3;
        const int Cout = (blk == 0) ? 16 : 20;
        const int d    = (blk == 0) ? 75 : (blk == 1) ? 400 : 500;
        int* khp = g_kh + blk * 32;

        __shared__ float norms[32];
        __shared__ float smx;
        int w = threadIdx.x >> 5, lane = threadIdx.x & 31;

        for (int f = w; f < Cout; f += 8) {
            float s = 0.f;
            for (int j = lane; j < d; j += 32) { float v = W[f * d + j]; s += v * v; }
            #pragma unroll
            for (int off = 16; off; off >>= 1)
                s += __shfl_xor_sync(0xffffffffu, s, off);
            if (lane == 0) norms[f] = sqrtf(s);
        }
        __syncthreads();
        if (threadIdx.x < 32) {
            float v = (lane < Cout) ? norms[lane] : 0.f;
            #pragma unroll
            for (int off = 16; off; off >>= 1)
                v = fmaxf(v, __shfl_xor_sync(0xffffffffu, v, off));
            if (lane == 0) smx = v;
        }
        __syncthreads();
        const float scale = 1.f / (smx + EPSF);
        for (int f = w; f < Cout; f += 8) {
            float dot = 0.f, ss = 0.f;
            for (int j = lane; j < d; j += 32) {
                float v = W[f * d + j] * scale;
                dot += v * a[j];
                ss  += v * v;
            }
            #pragma unroll
            for (int off = 16; off; off >>= 1) {
                dot += __shfl_xor_sync(0xffffffffu, dot, off);
                ss  += __shfl_xor_sync(0xffffffffu, ss, off);
            }
            if (lane == 0) {
                float n = sqrtf(ss), p = n;
                #pragma unroll
                for (int m = 0; m < 5; m++) { p = p * p; dot += p * a[d + m]; }
                dot += c[0];
                long long fl = (long long)floorf(dot / R_HASH);
                khp[f] = (int)(((fl % 2) + 2) % 2);
            }
        }
    } else {
        const int t = threadIdx.x;
        if (blk == 3) {
            if (t < 16) {
                float s = 0.f; for (int j = 0; j < 25; j++) s += a2[t * 25 + j];
                g_aux[t] = s;
            } else if (t >= 32 && t < 52) {
                int r = t - 32;
                float s = 0.f; for (int j = 0; j < 25; j++) s += a3[r * 25 + j];
                g_aux[16 + r] = s;
            } else if (t >= 64 && t < 67) {
                int r = t - 64;
                float s = 0.f; for (int j = 0; j < 25; j++) s += a1[r * 25 + j];
                g_aux[38 + r] = s;
            } else if (t == 67) {
                float s = 0.f; for (int m = 0; m < 5; m++) s += a2[400 + m];
                g_aux[36] = s;
            } else if (t == 68) {
                float s = 0.f; for (int m = 0; m < 5; m++) s += a3[500 + m];
                g_aux[37] = s;
            } else if (t == 69) {
                float s = 0.f; for (int m = 0; m < 5; m++) s += a1[75 + m];
                g_aux[41] = s;
            }
        }
        const int base = (blk - 3) * 256 + t;
        const int stride = 5 * 256;
        for (int i = base; i < 48 * 28; i += stride) {
            int f = i / 28, k = i % 28;
            g_w1p[i] = (k < 25) ? W1[f * 25 + k] : 0.f;
        }
        for (int i = base; i < 320 * 28; i += stride) {
            int f = i / 28, k = i % 28;
            g_w2p[i] = (k < 25) ? W2[f * 25 + k] : 0.f;
        }
        for (int i = base; i < 400 * 28; i += stride) {
            int f = i / 28, k = i % 28;
            g_w3p[i] = (k < 25) ? W3[f * 25 + k] : 0.f;
        }
    }
}

// ---------------------------------------------------------------------------
// Layer-1 query hash: one warp per sample
// ---------------------------------------------------------------------------
__global__ __launch_bounds__(256)
void qh1_kernel(const float* __restrict__ x, const float* __restrict__ c1,
                int* __restrict__ qh_out)
{
    int warp = threadIdx.x >> 5, lane = threadIdx.x & 31;
    int b = blockIdx.x * 8 + warp;
    const float4* xb = (const float4*)(x + (size_t)b * 3072);
    float s[3];
    #pragma unroll
    for (int c = 0; c < 3; c++) {
        float p = 0.f;
        #pragma unroll
        for (int i = lane; i < 256; i += 32) {
            float4 v = xb[c * 256 + i];
            p += (v.x + v.y) + (v.z + v.w);
        }
        #pragma unroll
        for (int off = 16; off; off >>= 1)
            p += __shfl_xor_sync(0xffffffffu, p, off);
        s[c] = p;
    }
    if (lane == 0) {
        float dot = 0.f, ss = 0.f;
        #pragma unroll
        for (int c = 0; c < 3; c++) {
            float cm = s[c] * (1.f / 1024.f);
            dot += cm * g_aux[38 + c];
            ss  += cm * cm;
        }
        float v = dot / (sqrtf(25.f * ss) + EPSF) + 0.5f * g_aux[41] + c1[0];
        long long f = (long long)floorf(v / R_HASH);
        qh_out[b] = (int)(((f % 2) + 2) % 2);
    }
}

// ---------------------------------------------------------------------------
// Fused conv5x5(pad2)+bias+relu+mask+maxpool2 (R7/R11 mainloop).
// Compacted active-channel x tiles in smem; padded weights via 7x float4 __ldg.
// NOPREV=true specializes n_ci==CIN (identity channel map, no indirection).
// ---------------------------------------------------------------------------
template <int CIN, int COUT, int H, int W, int WPAD, int SPB, int T, int MINB,
          bool EPI, bool NOPREV>
__global__ __launch_bounds__(T, MINB)
void conv_fused(const float* __restrict__ in, float* __restrict__ out,
                const float* __restrict__ wpad, const float* __restrict__ bias,
                const int* __restrict__ kh, const int* __restrict__ qh,
                const int* __restrict__ kh_prev, const int* __restrict__ qh_prev,
                const float* __restrict__ asum_next,
                const float* __restrict__ tail_next,
                const float* __restrict__ c_next, int* __restrict__ qh_next)
{
    constexpr int HP = H + 4;
    constexpr int PH = H / 2, PW = W / 2, PX2 = PW / 2;
    constexpr int PP = PH * PX2;
    constexpr int SEG = (PP < 32) ? PP : 32;
    constexpr int CHW = HP * WPAD;

    extern __shared__ float sm[];
    float* sx  = sm;
    float* scm = sx + SPB * CIN * CHW;
    int* nact  = (int*)(scm + SPB * COUT);
    int* soff  = nact + SPB;
    int* actco = soff + SPB + 1;
    int* nci   = actco + SPB * COUT;
    int* actci = nci + SPB;
    int* sxoff = actci + SPB * CIN;

    const int b0 = blockIdx.x * SPB;
    const int t  = threadIdx.x;

    if (t < SPB) {
        int s = t, n = 0, qv = qh[b0 + s];
        for (int co = 0; co < COUT; co++)
            if (kh[co] == qv) actco[s * COUT + n++] = co;
        nact[s] = n;
    } else if (t >= 32 && t < 32 + SPB) {
        int s = t - 32, n = 0;
        if (!NOPREV) {
            int qv = qh_prev[b0 + s];
            for (int c = 0; c < CIN; c++)
                if (kh_prev[c] == qv) actci[s * CIN + n++] = c;
        } else {
            for (int c = 0; c < CIN; c++) actci[s * CIN + n++] = c;
        }
        nci[s] = n;
    }
    if (EPI) for (int i = t; i < SPB * COUT; i += T) scm[i] = 0.f;
    __syncthreads();
    if (t == 0) {
        int o = 0, xo = 0;
        for (int s = 0; s < SPB; s++) {
            soff[s] = o;  o  += nact[s] * PP;
            sxoff[s] = xo; xo += NOPREV ? CIN : nci[s];
        }
        soff[SPB] = o; sxoff[SPB] = xo;
    }
    __syncthreads();

    const int total_ch = sxoff[SPB];
    for (int i = t; i < total_ch * CHW; i += T) {
        int pos = i % CHW, ch = i / CHW;
        int s = 0;
        #pragma unroll
        for (int ss = 0; ss < SPB - 1; ss++)
            if (ch >= sxoff[ss + 1]) s = ss + 1;
        int c = NOPREV ? (ch - sxoff[s]) : actci[s * CIN + (ch - sxoff[s])];
        int py = pos / WPAD, px = pos % WPAD;
        int y = py - 2, x = px - 2;
        float v = 0.f;
        if ((unsigned)y < (unsigned)H && (unsigned)x < (unsigned)W)
            v = in[((size_t)(b0 + s) * CIN + c) * (H * W) + y * W + x];
        sx[i] = v;
    }
    __syncthreads();
    const int total = soff[SPB];

    for (int item = t;; item += T) {
        if (!__ballot_sync(0xffffffffu, item < total)) break;
        float val = 0.f;
        int s = 0, co = 0;
        if (item < total) {
            #pragma unroll
            for (int ss = 0; ss < SPB - 1; ss++)
                if (item >= soff[ss + 1]) s = ss + 1;
            int local = item - soff[s];
            co = actco[s * COUT + local / PP];
            int rr = local % PP;
            int py = rr / PX2, px2 = rr % PX2;

            float acc[2][4] = {};
            const float* xb = sx + (size_t)sxoff[s] * CHW + (2 * py) * WPAD + 4 * px2;
            const int n_ci = NOPREV ? CIN : nci[s];
            const int* ci = actci + s * CIN;
            const float* wb_ = wpad + (size_t)co * CIN * 28;

            for (int j = 0; j < n_ci; j++) {
                int c = NOPREV ? j : ci[j];
                const float4* wr = (const float4*)(wb_ + c * 28);
                float4 q0 = __ldg(wr + 0), q1 = __ldg(wr + 1), q2 = __ldg(wr + 2);
                float4 q3 = __ldg(wr + 3), q4 = __ldg(wr + 4), q5 = __ldg(wr + 5);
                float4 q6 = __ldg(wr + 6);
                float w[25] = {q0.x, q0.y, q0.z, q0.w, q1.x, q1.y, q1.z, q1.w,
                               q2.x, q2.y, q2.z, q2.w, q3.x, q3.y, q3.z, q3.w,
                               q4.x, q4.y, q4.z, q4.w, q5.x, q5.y, q5.z, q5.w,
                               q6.x};
                const float* xs = xb + j * CHW;
                #pragma unroll
                for (int rw = 0; rw < 6; rw++) {
                    float4 x0 = *(const float4*)(xs + rw * WPAD);
                    float4 x1 = *(const float4*)(xs + rw * WPAD + 4);
                    float xr[8] = {x0.x, x0.y, x0.z, x0.w, x1.x, x1.y, x1.z, x1.w};
                    if (rw < 5) {
                        #pragma unroll
                        for (int kx = 0; kx < 5; kx++) {
                            float wa = w[rw * 5 + kx];
                            acc[0][0] += xr[kx + 0] * wa;
                            acc[0][1] += xr[kx + 1] * wa;
                            acc[0][2] += xr[kx + 2] * wa;
                            acc[0][3] += xr[kx + 3] * wa;
                        }
                    }
                    if (rw > 0) {
                        #pragma unroll
                        for (int kx = 0; kx < 5; kx++) {
                            float wb = w[(rw - 1) * 5 + kx];
                            acc[1][0] += xr[kx + 0] * wb;
                            acc[1][1] += xr[kx + 1] * wb;
                            acc[1][2] += xr[kx + 2] * wb;
                            acc[1][3] += xr[kx + 3] * wb;
                        }
                    }
                }
            }
            float bv = __ldg(bias + co);
            float v00 = fmaxf(acc[0][0] + bv, 0.f), v01 = fmaxf(acc[0][1] + bv, 0.f);
            float v02 = fmaxf(acc[0][2] + bv, 0.f), v03 = fmaxf(acc[0][3] + bv, 0.f);
            float v10 = fmaxf(acc[1][0] + bv, 0.f), v11 = fmaxf(acc[1][1] + bv, 0.f);
            float v12 = fmaxf(acc[1][2] + bv, 0.f), v13 = fmaxf(acc[1][3] + bv, 0.f);
            float o0 = fmaxf(fmaxf(v00, v01), fmaxf(v10, v11));
            float o1 = fmaxf(fmaxf(v02, v03), fmaxf(v12, v13));
            float2* op = (float2*)&out[(((size_t)(b0 + s) * COUT + co) * PH + py) * PW + px2 * 2];
            *op = make_float2(o0, o1);
            val = o0 + o1;
        }
        if (EPI) {
            #pragma unroll
            for (int off = SEG / 2; off; off >>= 1)
                val += __shfl_xor_sync(0xffffffffu, val, off);
            if ((t & (SEG - 1)) == 0 && item < total)
                atomicAdd(&scm[s * COUT + co], val);
        }
    }

    if (EPI) {
        __syncthreads();
        if (t < SPB) {
            int s = t;
            float dot = 0.f, ssum = 0.f;
            const float inv = 1.f / (float)(PH * PW);
            for (int c = 0; c < COUT; c++) {
                float cm = scm[s * COUT + c] * inv;
                dot  += cm * asum_next[c];
                ssum += cm * cm;
            }
            float v = dot / (sqrtf(25.f * ssum) + EPSF) + 0.5f * tail_next[0] + c_next[0];
            long long f = (long long)floorf(v / R_HASH);
            qh_next[b0 + s] = (int)(((f % 2) + 2) % 2);
        }
    }
}

// ---------------------------------------------------------------------------
// FC with layer-3 mask applied on load
// ---------------------------------------------------------------------------
__global__ __launch_bounds__(256)
void fc_kernel(const float* __restrict__ h, const float* __restrict__ Wo,
               const float* __restrict__ bo, float* __restrict__ out,
               const int* __restrict__ kh3, const int* __restrict__ qh3)
{
    __shared__ float sW[3200];
    __shared__ float sb[10];
    __shared__ int skh[20];
    int t = threadIdx.x;
    for (int i = t; i < 3200; i += 256) sW[i] = Wo[i];
    if (t < 10) sb[t] = bo[t];
    if (t < 20) skh[t] = kh3[t];
    __syncthreads();
    int warp = t / 32, lane = t % 32;
    int b = blockIdx.x * 8 + warp;
    int qv = qh3[b];
    const float* hb = h + (size_t)b * 320;
    float x[10];
    #pragma unroll
    for (int j = 0; j < 10; j++) {
        int idx = lane + j * 32;
        x[j] = (skh[idx >> 4] == qv) ? hb[idx] : 0.f;
    }
    #pragma unroll
    for (int o = 0; o < 10; o++) {
        float p = 0.f;
        #pragma unroll
        for (int j = 0; j < 10; j++) p += x[j] * sW[o * 320 + lane + j * 32];
        #pragma unroll
        for (int off = 16; off; off >>= 1) p += __shfl_xor_sync(0xffffffffu, p, off);
        if (lane == 0) out[b * 10 + o] = p + sb[o];
    }
}

// ---------------------------------------------------------------------------
static inline int smem_bytes(int CIN, int COUT, int SPB, int HP, int WPAD)
{
    int fl = SPB * CIN * HP * WPAD + SPB * COUT;
    int it = SPB + (SPB + 1) + SPB * COUT + SPB + SPB * CIN + (SPB + 1);
    return 4 * (fl + it);
}

extern "C" void kernel_launch(void* const* d_in, const int* in_sizes, int n_in,
                              void* d_out, int out_size)
{
    const float* x  = (const float*)d_in[0];
    const float* W1 = (const float*)d_in[1];
    const float* b1 = (const float*)d_in[2];
    const float* a1 = (const float*)d_in[3];
    const float* c1 = (const float*)d_in[4];
    const float* W2 = (const float*)d_in[5];
    const float* b2 = (const float*)d_in[6];
    const float* a2 = (const float*)d_in[7];
    const float* c2 = (const float*)d_in[8];
    const float* W3 = (const float*)d_in[9];
    const float* b3 = (const float*)d_in[10];
    const float* a3 = (const float*)d_in[11];
    const float* c3 = (const float*)d_in[12];
    const float* Wo = (const float*)d_in[13];
    const float* bo = (const float*)d_in[14];
    float* out = (float*)d_out;

    float *h1, *h2, *h3, *aux, *w1p, *w2p, *w3p; int *qh, *kh;
    cudaGetSymbolAddress((void**)&h1, g_h1);
    cudaGetSymbolAddress((void**)&h2, g_h2);
    cudaGetSymbolAddress((void**)&h3, g_h3);
    cudaGetSymbolAddress((void**)&qh, g_qh);
    cudaGetSymbolAddress((void**)&kh, g_kh);
    cudaGetSymbolAddress((void**)&aux, g_aux);
    cudaGetSymbolAddress((void**)&w1p, g_w1p);
    cudaGetSymbolAddress((void**)&w2p, g_w2p);
    cudaGetSymbolAddress((void**)&w3p, g_w3p);

    const int sm1 = smem_bytes(3, 16, 1, 36, 36);
    const int sm2 = smem_bytes(16, 20, 1, 20, 24);
    const int sm3 = smem_bytes(20, 20, 2, 12, 12);

    cudaFuncSetAttribute((const void*)conv_fused<3, 16, 32, 32, 36, 1, 256, 4, true, true>,
                         cudaFuncAttributeMaxDynamicSharedMemorySize, sm1);
    cudaFuncSetAttribute((const void*)conv_fused<16, 20, 16, 16, 24, 1, 160, 6, true, false>,
                         cudaFuncAttributeMaxDynamicSharedMemorySize, sm2);
    cudaFuncSetAttribute((const void*)conv_fused<20, 20, 8, 8, 12, 2, 160, 6, false, false>,
                         cudaFuncAttributeMaxDynamicSharedMemorySize, sm3);

    kh_all<<<8, 256>>>(W1, a1, c1, W2, a2, c2, W3, a3, c3);
    qh1_kernel<<<BATCH / 8, 256>>>(x, c1, qh);

    conv_fused<3, 16, 32, 32, 36, 1, 256, 4, true, true><<<BATCH, 256, sm1>>>(
        x, h1, w1p, b1, kh, qh, nullptr, nullptr,
        aux + 0, aux + 36, c2, qh + BATCH);

    conv_fused<16, 20, 16, 16, 24, 1, 160, 6, true, false><<<BATCH, 160, sm2>>>(
        h1, h2, w2p, b2, kh + 32, qh + BATCH, kh, qh,
        aux + 16, aux + 37, c3, qh + 2 * BATCH);

    conv_fused<20, 20, 8, 8, 12, 2, 160, 6, false, false><<<BATCH / 2, 160, sm3>>>(
        h2, h3, w3p, b3, kh + 64, qh + 2 * BATCH, kh + 32, qh + BATCH,
        nullptr, nullptr, nullptr, nullptr);

    fc_kernel<<<BATCH / 8, 256>>>(h3, Wo, bo, out, kh + 64, qh + 2 * BATCH);
}

// round 14
// speedup vs baseline: 1.6691x; 1.2036x over previous
#include <cuda_runtime.h>
#include <math.h>

#define R_HASH 0.2f
#define EPSF   1e-12f
#define BATCH  4096

// scratch (device globals: sanctioned scratch mechanism)
__device__ float g_h1[BATCH * 16 * 16 * 16];
__device__ float g_h2[BATCH * 20 * 8 * 8];
__device__ float g_h3[BATCH * 20 * 4 * 4];
__device__ int   g_qh[3 * BATCH];
__device__ int   g_kh[96];
__device__ float g_aux[48];
__device__ __align__(16) float g_w1p[48 * 28];   // padded weights, stride 28
__device__ __align__(16) float g_w2p[320 * 28];
__device__ __align__(16) float g_w3p[400 * 28];

// ---------------------------------------------------------------------------
// Fused setup kernel: blocks 0-2 = filter hashes (one warp per filter,
// lane-parallel dot products); blocks 3-7 = weight padding + aux sums.
// ---------------------------------------------------------------------------
__global__ void kh_all(const float* __restrict__ W1, const float* __restrict__ a1,
                       const float* __restrict__ c1,
                       const float* __restrict__ W2, const float* __restrict__ a2,
                       const float* __restrict__ c2,
                       const float* __restrict__ W3, const float* __restrict__ a3,
                       const float* __restrict__ c3)
{
    const int blk = blockIdx.x;
    if (blk < 3) {
        const float* W = (blk == 0) ? W1 : (blk == 1) ? W2 : W3;
        const float* a = (blk == 0) ? a1 : (blk == 1) ? a2 : a3;
        const float* c = (blk == 0) ? c1 : (blk == 1) ? c2 : c3;
        const int Cout = (blk == 0) ? 16 : 20;
        const int d    = (blk == 0) ? 75 : (blk == 1) ? 400 : 500;
        int* khp = g_kh + blk * 32;

        __shared__ float norms[32];
        __shared__ float smx;
        int w = threadIdx.x >> 5, lane = threadIdx.x & 31;

        for (int f = w; f < Cout; f += 8) {
            float s = 0.f;
            for (int j = lane; j < d; j += 32) { float v = W[f * d + j]; s += v * v; }
            #pragma unroll
            for (int off = 16; off; off >>= 1)
                s += __shfl_xor_sync(0xffffffffu, s, off);
            if (lane == 0) norms[f] = sqrtf(s);
        }
        __syncthreads();
        if (threadIdx.x < 32) {
            float v = (lane < Cout) ? norms[lane] : 0.f;
            #pragma unroll
            for (int off = 16; off; off >>= 1)
                v = fmaxf(v, __shfl_xor_sync(0xffffffffu, v, off));
            if (lane == 0) smx = v;
        }
        __syncthreads();
        const float scale = 1.f / (smx + EPSF);
        for (int f = w; f < Cout; f += 8) {
            float dot = 0.f, ss = 0.f;
            for (int j = lane; j < d; j += 32) {
                float v = W[f * d + j] * scale;
                dot += v * a[j];
                ss  += v * v;
            }
            #pragma unroll
            for (int off = 16; off; off >>= 1) {
                dot += __shfl_xor_sync(0xffffffffu, dot, off);
                ss  += __shfl_xor_sync(0xffffffffu, ss, off);
            }
            if (lane == 0) {
                float n = sqrtf(ss), p = n;
                #pragma unroll
                for (int m = 0; m < 5; m++) { p = p * p; dot += p * a[d + m]; }
                dot += c[0];
                long long fl = (long long)floorf(dot / R_HASH);
                khp[f] = (int)(((fl % 2) + 2) % 2);
            }
        }
    } else {
        const int t = threadIdx.x;
        if (blk == 3) {
            if (t < 16) {
                float s = 0.f; for (int j = 0; j < 25; j++) s += a2[t * 25 + j];
                g_aux[t] = s;
            } else if (t >= 32 && t < 52) {
                int r = t - 32;
                float s = 0.f; for (int j = 0; j < 25; j++) s += a3[r * 25 + j];
                g_aux[16 + r] = s;
            } else if (t >= 64 && t < 67) {
                int r = t - 64;
                float s = 0.f; for (int j = 0; j < 25; j++) s += a1[r * 25 + j];
                g_aux[38 + r] = s;
            } else if (t == 67) {
                float s = 0.f; for (int m = 0; m < 5; m++) s += a2[400 + m];
                g_aux[36] = s;
            } else if (t == 68) {
                float s = 0.f; for (int m = 0; m < 5; m++) s += a3[500 + m];
                g_aux[37] = s;
            } else if (t == 69) {
                float s = 0.f; for (int m = 0; m < 5; m++) s += a1[75 + m];
                g_aux[41] = s;
            }
        }
        const int base = (blk - 3) * 256 + t;
        const int stride = 5 * 256;
        for (int i = base; i < 48 * 28; i += stride) {
            int f = i / 28, k = i % 28;
            g_w1p[i] = (k < 25) ? W1[f * 25 + k] : 0.f;
        }
        for (int i = base; i < 320 * 28; i += stride) {
            int f = i / 28, k = i % 28;
            g_w2p[i] = (k < 25) ? W2[f * 25 + k] : 0.f;
        }
        for (int i = base; i < 400 * 28; i += stride) {
            int f = i / 28, k = i % 28;
            g_w3p[i] = (k < 25) ? W3[f * 25 + k] : 0.f;
        }
    }
}

// ---------------------------------------------------------------------------
// Layer-1 query hash: one warp per sample
// ---------------------------------------------------------------------------
__global__ __launch_bounds__(256)
void qh1_kernel(const float* __restrict__ x, const float* __restrict__ c1,
                int* __restrict__ qh_out)
{
    int warp = threadIdx.x >> 5, lane = threadIdx.x & 31;
    int b = blockIdx.x * 8 + warp;
    const float4* xb = (const float4*)(x + (size_t)b * 3072);
    float s[3];
    #pragma unroll
    for (int c = 0; c < 3; c++) {
        float p = 0.f;
        #pragma unroll
        for (int i = lane; i < 256; i += 32) {
            float4 v = xb[c * 256 + i];
            p += (v.x + v.y) + (v.z + v.w);
        }
        #pragma unroll
        for (int off = 16; off; off >>= 1)
            p += __shfl_xor_sync(0xffffffffu, p, off);
        s[c] = p;
    }
    if (lane == 0) {
        float dot = 0.f, ss = 0.f;
        #pragma unroll
        for (int c = 0; c < 3; c++) {
            float cm = s[c] * (1.f / 1024.f);
            dot += cm * g_aux[38 + c];
            ss  += cm * cm;
        }
        float v = dot / (sqrtf(25.f * ss) + EPSF) + 0.5f * g_aux[41] + c1[0];
        long long f = (long long)floorf(v / R_HASH);
        qh_out[b] = (int)(((f % 2) + 2) % 2);
    }
}

// ---------------------------------------------------------------------------
// Fused conv5x5(pad2)+bias+relu+mask+maxpool2 (R7/R11 mainloop).
// Staging: zero-fill tile (float4 STS), then interior rows via float4 LDG.
// NOPREV=true specializes n_ci==CIN (identity channel map, no indirection).
// ---------------------------------------------------------------------------
template <int CIN, int COUT, int H, int W, int WPAD, int SPB, int T, int MINB,
          bool EPI, bool NOPREV>
__global__ __launch_bounds__(T, MINB)
void conv_fused(const float* __restrict__ in, float* __restrict__ out,
                const float* __restrict__ wpad, const float* __restrict__ bias,
                const int* __restrict__ kh, const int* __restrict__ qh,
                const int* __restrict__ kh_prev, const int* __restrict__ qh_prev,
                const float* __restrict__ asum_next,
                const float* __restrict__ tail_next,
                const float* __restrict__ c_next, int* __restrict__ qh_next)
{
    constexpr int HP = H + 4;
    constexpr int PH = H / 2, PW = W / 2, PX2 = PW / 2;
    constexpr int PP = PH * PX2;
    constexpr int SEG = (PP < 32) ? PP : 32;
    constexpr int CHW = HP * WPAD;
    constexpr int WG = W / 4;                 // float4 groups per row

    extern __shared__ float sm[];
    float* sx  = sm;
    float* scm = sx + SPB * CIN * CHW;
    int* nact  = (int*)(scm + SPB * COUT);
    int* soff  = nact + SPB;
    int* actco = soff + SPB + 1;
    int* nci   = actco + SPB * COUT;
    int* actci = nci + SPB;
    int* sxoff = actci + SPB * CIN;

    const int b0 = blockIdx.x * SPB;
    const int t  = threadIdx.x;

    if (t < SPB) {
        int s = t, n = 0, qv = qh[b0 + s];
        for (int co = 0; co < COUT; co++)
            if (kh[co] == qv) actco[s * COUT + n++] = co;
        nact[s] = n;
    } else if (t >= 32 && t < 32 + SPB) {
        int s = t - 32, n = 0;
        if (!NOPREV) {
            int qv = qh_prev[b0 + s];
            for (int c = 0; c < CIN; c++)
                if (kh_prev[c] == qv) actci[s * CIN + n++] = c;
        } else {
            for (int c = 0; c < CIN; c++) actci[s * CIN + n++] = c;
        }
        nci[s] = n;
    }
    if (EPI) for (int i = t; i < SPB * COUT; i += T) scm[i] = 0.f;
    __syncthreads();
    if (t == 0) {
        int o = 0, xo = 0;
        for (int s = 0; s < SPB; s++) {
            soff[s] = o;  o  += nact[s] * PP;
            sxoff[s] = xo; xo += NOPREV ? CIN : nci[s];
        }
        soff[SPB] = o; sxoff[SPB] = xo;
    }
    __syncthreads();

    const int total_ch = sxoff[SPB];
    // zero-fill used portion of tile (float4 STS)
    {
        float4 z = make_float4(0.f, 0.f, 0.f, 0.f);
        float4* sx4 = (float4*)sx;
        const int n4 = total_ch * (CHW / 4);
        for (int i = t; i < n4; i += T) sx4[i] = z;
    }
    __syncthreads();
    // interior rows via float4 LDG + 4 scalar STS
    for (int i = t; i < total_ch * H * WG; i += T) {
        int xg = i % WG; int rest = i / WG;
        int y = rest % H; int ch = rest / H;
        int s = 0;
        #pragma unroll
        for (int ss = 0; ss < SPB - 1; ss++)
            if (ch >= sxoff[ss + 1]) s = ss + 1;
        int c = NOPREV ? (ch - sxoff[s]) : actci[s * CIN + (ch - sxoff[s])];
        float4 v = *(const float4*)(in + ((size_t)(b0 + s) * CIN + c) * (H * W)
                                    + y * W + 4 * xg);
        float* dst = sx + ch * CHW + (y + 2) * WPAD + 4 * xg + 2;
        dst[0] = v.x; dst[1] = v.y; dst[2] = v.z; dst[3] = v.w;
    }
    __syncthreads();
    const int total = soff[SPB];

    for (int item = t;; item += T) {
        if (!__ballot_sync(0xffffffffu, item < total)) break;
        float val = 0.f;
        int s = 0, co = 0;
        if (item < total) {
            #pragma unroll
            for (int ss = 0; ss < SPB - 1; ss++)
                if (item >= soff[ss + 1]) s = ss + 1;
            int local = item - soff[s];
            co = actco[s * COUT + local / PP];
            int rr = local % PP;
            int py = rr / PX2, px2 = rr % PX2;

            float acc[2][4] = {};
            const float* xb = sx + (size_t)sxoff[s] * CHW + (2 * py) * WPAD + 4 * px2;
            const int n_ci = NOPREV ? CIN : nci[s];
            const int* ci = actci + s * CIN;
            const float* wb_ = wpad + (size_t)co * CIN * 28;

            for (int j = 0; j < n_ci; j++) {
                int c = NOPREV ? j : ci[j];
                const float4* wr = (const float4*)(wb_ + c * 28);
                float4 q0 = __ldg(wr + 0), q1 = __ldg(wr + 1), q2 = __ldg(wr + 2);
                float4 q3 = __ldg(wr + 3), q4 = __ldg(wr + 4), q5 = __ldg(wr + 5);
                float4 q6 = __ldg(wr + 6);
                float w[25] = {q0.x, q0.y, q0.z, q0.w, q1.x, q1.y, q1.z, q1.w,
                               q2.x, q2.y, q2.z, q2.w, q3.x, q3.y, q3.z, q3.w,
                               q4.x, q4.y, q4.z, q4.w, q5.x, q5.y, q5.z, q5.w,
                               q6.x};
                const float* xs = xb + j * CHW;
                #pragma unroll
                for (int rw = 0; rw < 6; rw++) {
                    float4 x0 = *(const float4*)(xs + rw * WPAD);
                    float4 x1 = *(const float4*)(xs + rw * WPAD + 4);
                    float xr[8] = {x0.x, x0.y, x0.z, x0.w, x1.x, x1.y, x1.z, x1.w};
                    if (rw < 5) {
                        #pragma unroll
                        for (int kx = 0; kx < 5; kx++) {
                            float wa = w[rw * 5 + kx];
                            acc[0][0] += xr[kx + 0] * wa;
                            acc[0][1] += xr[kx + 1] * wa;
                            acc[0][2] += xr[kx + 2] * wa;
                            acc[0][3] += xr[kx + 3] * wa;
                        }
                    }
                    if (rw > 0) {
                        #pragma unroll
                        for (int kx = 0; kx < 5; kx++) {
                            float wb = w[(rw - 1) * 5 + kx];
                            acc[1][0] += xr[kx + 0] * wb;
                            acc[1][1] += xr[kx + 1] * wb;
                            acc[1][2] += xr[kx + 2] * wb;
                            acc[1][3] += xr[kx + 3] * wb;
                        }
                    }
                }
            }
            float bv = __ldg(bias + co);
            float v00 = fmaxf(acc[0][0] + bv, 0.f), v01 = fmaxf(acc[0][1] + bv, 0.f);
            float v02 = fmaxf(acc[0][2] + bv, 0.f), v03 = fmaxf(acc[0][3] + bv, 0.f);
            float v10 = fmaxf(acc[1][0] + bv, 0.f), v11 = fmaxf(acc[1][1] + bv, 0.f);
            float v12 = fmaxf(acc[1][2] + bv, 0.f), v13 = fmaxf(acc[1][3] + bv, 0.f);
            float o0 = fmaxf(fmaxf(v00, v01), fmaxf(v10, v11));
            float o1 = fmaxf(fmaxf(v02, v03), fmaxf(v12, v13));
            float2* op = (float2*)&out[(((size_t)(b0 + s) * COUT + co) * PH + py) * PW + px2 * 2];
            *op = make_float2(o0, o1);
            val = o0 + o1;
        }
        if (EPI) {
            #pragma unroll
            for (int off = SEG / 2; off; off >>= 1)
                val += __shfl_xor_sync(0xffffffffu, val, off);
            if ((t & (SEG - 1)) == 0 && item < total)
                atomicAdd(&scm[s * COUT + co], val);
        }
    }

    if (EPI) {
        __syncthreads();
        if (t < SPB) {
            int s = t;
            float dot = 0.f, ssum = 0.f;
            const float inv = 1.f / (float)(PH * PW);
            for (int c = 0; c < COUT; c++) {
                float cm = scm[s * COUT + c] * inv;
                dot  += cm * asum_next[c];
                ssum += cm * cm;
            }
            float v = dot / (sqrtf(25.f * ssum) + EPSF) + 0.5f * tail_next[0] + c_next[0];
            long long f = (long long)floorf(v / R_HASH);
            qh_next[b0 + s] = (int)(((f % 2) + 2) % 2);
        }
    }
}

// ---------------------------------------------------------------------------
// FC with layer-3 mask applied on load
// ---------------------------------------------------------------------------
__global__ __launch_bounds__(256)
void fc_kernel(const float* __restrict__ h, const float* __restrict__ Wo,
               const float* __restrict__ bo, float* __restrict__ out,
               const int* __restrict__ kh3, const int* __restrict__ qh3)
{
    __shared__ float sW[3200];
    __shared__ float sb[10];
    __shared__ int skh[20];
    int t = threadIdx.x;
    for (int i = t; i < 3200; i += 256) sW[i] = Wo[i];
    if (t < 10) sb[t] = bo[t];
    if (t < 20) skh[t] = kh3[t];
    __syncthreads();
    int warp = t / 32, lane = t % 32;
    int b = blockIdx.x * 8 + warp;
    int qv = qh3[b];
    const float* hb = h + (size_t)b * 320;
    float x[10];
    #pragma unroll
    for (int j = 0; j < 10; j++) {
        int idx = lane + j * 32;
        x[j] = (skh[idx >> 4] == qv) ? hb[idx] : 0.f;
    }
    #pragma unroll
    for (int o = 0; o < 10; o++) {
        float p = 0.f;
        #pragma unroll
        for (int j = 0; j < 10; j++) p += x[j] * sW[o * 320 + lane + j * 32];
        #pragma unroll
        for (int off = 16; off; off >>= 1) p += __shfl_xor_sync(0xffffffffu, p, off);
        if (lane == 0) out[b * 10 + o] = p + sb[o];
    }
}

// ---------------------------------------------------------------------------
static inline int smem_bytes(int CIN, int COUT, int SPB, int HP, int WPAD)
{
    int fl = SPB * CIN * HP * WPAD + SPB * COUT;
    int it = SPB + (SPB + 1) + SPB * COUT + SPB + SPB * CIN + (SPB + 1);
    return 4 * (fl + it);
}

extern "C" void kernel_launch(void* const* d_in, const int* in_sizes, int n_in,
                              void* d_out, int out_size)
{
    const float* x  = (const float*)d_in[0];
    const float* W1 = (const float*)d_in[1];
    const float* b1 = (const float*)d_in[2];
    const float* a1 = (const float*)d_in[3];
    const float* c1 = (const float*)d_in[4];
    const float* W2 = (const float*)d_in[5];
    const float* b2 = (const float*)d_in[6];
    const float* a2 = (const float*)d_in[7];
    const float* c2 = (const float*)d_in[8];
    const float* W3 = (const float*)d_in[9];
    const float* b3 = (const float*)d_in[10];
    const float* a3 = (const float*)d_in[11];
    const float* c3 = (const float*)d_in[12];
    const float* Wo = (const float*)d_in[13];
    const float* bo = (const float*)d_in[14];
    float* out = (float*)d_out;

    float *h1, *h2, *h3, *aux, *w1p, *w2p, *w3p; int *qh, *kh;
    cudaGetSymbolAddress((void**)&h1, g_h1);
    cudaGetSymbolAddress((void**)&h2, g_h2);
    cudaGetSymbolAddress((void**)&h3, g_h3);
    cudaGetSymbolAddress((void**)&qh, g_qh);
    cudaGetSymbolAddress((void**)&kh, g_kh);
    cudaGetSymbolAddress((void**)&aux, g_aux);
    cudaGetSymbolAddress((void**)&w1p, g_w1p);
    cudaGetSymbolAddress((void**)&w2p, g_w2p);
    cudaGetSymbolAddress((void**)&w3p, g_w3p);

    const int sm1 = smem_bytes(3, 16, 1, 36, 36);
    const int sm2 = smem_bytes(16, 20, 1, 20, 24);
    const int sm3 = smem_bytes(20, 20, 2, 12, 12);

    cudaFuncSetAttribute((const void*)conv_fused<3, 16, 32, 32, 36, 1, 256, 4, true, true>,
                         cudaFuncAttributeMaxDynamicSharedMemorySize, sm1);
    cudaFuncSetAttribute((const void*)conv_fused<16, 20, 16, 16, 24, 1, 160, 6, true, false>,
                         cudaFuncAttributeMaxDynamicSharedMemorySize, sm2);
    cudaFuncSetAttribute((const void*)conv_fused<20, 20, 8, 8, 12, 2, 160, 6, false, false>,
                         cudaFuncAttributeMaxDynamicSharedMemorySize, sm3);

    kh_all<<<8, 256>>>(W1, a1, c1, W2, a2, c2, W3, a3, c3);
    qh1_kernel<<<BATCH / 8, 256>>>(x, c1, qh);

    conv_fused<3, 16, 32, 32, 36, 1, 256, 4, true, true><<<BATCH, 256, sm1>>>(
        x, h1, w1p, b1, kh, qh, nullptr, nullptr,
        aux + 0, aux + 36, c2, qh + BATCH);

    conv_fused<16, 20, 16, 16, 24, 1, 160, 6, true, false><<<BATCH, 160, sm2>>>(
        h1, h2, w2p, b2, kh + 32, qh + BATCH, kh, qh,
        aux + 16, aux + 37, c3, qh + 2 * BATCH);

    conv_fused<20, 20, 8, 8, 12, 2, 160, 6, false, false><<<BATCH / 2, 160, sm3>>>(
        h2, h3, w3p, b3, kh + 64, qh + 2 * BATCH, kh + 32, qh + BATCH,
        nullptr, nullptr, nullptr, nullptr);

    fc_kernel<<<BATCH / 8, 256>>>(h3, Wo, bo, out, kh + 64, qh + 2 * BATCH);
}

// round 15
// speedup vs baseline: 1.7075x; 1.0230x over previous
#include <cuda_runtime.h>
#include <math.h>

#define R_HASH 0.2f
#define EPSF   1e-12f
#define BATCH  4096

// scratch (device globals: sanctioned scratch mechanism)
__device__ float g_h1[BATCH * 16 * 16 * 16];
__device__ float g_h2[BATCH * 20 * 8 * 8];
__device__ int   g_qh[3 * BATCH];
__device__ int   g_kh[96];
__device__ float g_aux[48];
__device__ __align__(16) float g_w1p[48 * 28];   // padded weights, stride 28
__device__ __align__(16) float g_w2p[320 * 28];
__device__ __align__(16) float g_w3p[400 * 28];

// ---------------------------------------------------------------------------
// Fused setup kernel: blocks 0-2 = filter hashes (one warp per filter,
// lane-parallel dot products); blocks 3-7 = weight padding + aux sums.
// ---------------------------------------------------------------------------
__global__ void kh_all(const float* __restrict__ W1, const float* __restrict__ a1,
                       const float* __restrict__ c1,
                       const float* __restrict__ W2, const float* __restrict__ a2,
                       const float* __restrict__ c2,
                       const float* __restrict__ W3, const float* __restrict__ a3,
                       const float* __restrict__ c3)
{
    const int blk = blockIdx.x;
    if (blk < 3) {
        const float* W = (blk == 0) ? W1 : (blk == 1) ? W2 : W3;
        const float* a = (blk == 0) ? a1 : (blk == 1) ? a2 : a3;
        const float* c = (blk == 0) ? c1 : (blk == 1) ? c2 : c3;
        const int Cout = (blk == 0) ? 16 : 20;
        const int d    = (blk == 0) ? 75 : (blk == 1) ? 400 : 500;
        int* khp = g_kh + blk * 32;

        __shared__ float norms[32];
        __shared__ float smx;
        int w = threadIdx.x >> 5, lane = threadIdx.x & 31;

        for (int f = w; f < Cout; f += 8) {
            float s = 0.f;
            for (int j = lane; j < d; j += 32) { float v = W[f * d + j]; s += v * v; }
            #pragma unroll
            for (int off = 16; off; off >>= 1)
                s += __shfl_xor_sync(0xffffffffu, s, off);
            if (lane == 0) norms[f] = sqrtf(s);
        }
        __syncthreads();
        if (threadIdx.x < 32) {
            float v = (lane < Cout) ? norms[lane] : 0.f;
            #pragma unroll
            for (int off = 16; off; off >>= 1)
                v = fmaxf(v, __shfl_xor_sync(0xffffffffu, v, off));
            if (lane == 0) smx = v;
        }
        __syncthreads();
        const float scale = 1.f / (smx + EPSF);
        for (int f = w; f < Cout; f += 8) {
            float dot = 0.f, ss = 0.f;
            for (int j = lane; j < d; j += 32) {
                float v = W[f * d + j] * scale;
                dot += v * a[j];
                ss  += v * v;
            }
            #pragma unroll
            for (int off = 16; off; off >>= 1) {
                dot += __shfl_xor_sync(0xffffffffu, dot, off);
                ss  += __shfl_xor_sync(0xffffffffu, ss, off);
            }
            if (lane == 0) {
                float n = sqrtf(ss), p = n;
                #pragma unroll
                for (int m = 0; m < 5; m++) { p = p * p; dot += p * a[d + m]; }
                dot += c[0];
                long long fl = (long long)floorf(dot / R_HASH);
                khp[f] = (int)(((fl % 2) + 2) % 2);
            }
        }
    } else {
        const int t = threadIdx.x;
        if (blk == 3) {
            if (t < 16) {
                float s = 0.f; for (int j = 0; j < 25; j++) s += a2[t * 25 + j];
                g_aux[t] = s;
            } else if (t >= 32 && t < 52) {
                int r = t - 32;
                float s = 0.f; for (int j = 0; j < 25; j++) s += a3[r * 25 + j];
                g_aux[16 + r] = s;
            } else if (t >= 64 && t < 67) {
                int r = t - 64;
                float s = 0.f; for (int j = 0; j < 25; j++) s += a1[r * 25 + j];
                g_aux[38 + r] = s;
            } else if (t == 67) {
                float s = 0.f; for (int m = 0; m < 5; m++) s += a2[400 + m];
                g_aux[36] = s;
            } else if (t == 68) {
                float s = 0.f; for (int m = 0; m < 5; m++) s += a3[500 + m];
                g_aux[37] = s;
            } else if (t == 69) {
                float s = 0.f; for (int m = 0; m < 5; m++) s += a1[75 + m];
                g_aux[41] = s;
            }
        }
        const int base = (blk - 3) * 256 + t;
        const int stride = 5 * 256;
        for (int i = base; i < 48 * 28; i += stride) {
            int f = i / 28, k = i % 28;
            g_w1p[i] = (k < 25) ? W1[f * 25 + k] : 0.f;
        }
        for (int i = base; i < 320 * 28; i += stride) {
            int f = i / 28, k = i % 28;
            g_w2p[i] = (k < 25) ? W2[f * 25 + k] : 0.f;
        }
        for (int i = base; i < 400 * 28; i += stride) {
            int f = i / 28, k = i % 28;
            g_w3p[i] = (k < 25) ? W3[f * 25 + k] : 0.f;
        }
    }
}

// ---------------------------------------------------------------------------
// Layer-1 query hash: one warp per sample
// ---------------------------------------------------------------------------
__global__ __launch_bounds__(256)
void qh1_kernel(const float* __restrict__ x, const float* __restrict__ c1,
                int* __restrict__ qh_out)
{
    int warp = threadIdx.x >> 5, lane = threadIdx.x & 31;
    int b = blockIdx.x * 8 + warp;
    const float4* xb = (const float4*)(x + (size_t)b * 3072);
    float s[3];
    #pragma unroll
    for (int c = 0; c < 3; c++) {
        float p = 0.f;
        #pragma unroll
        for (int i = lane; i < 256; i += 32) {
            float4 v = xb[c * 256 + i];
            p += (v.x + v.y) + (v.z + v.w);
        }
        #pragma unroll
        for (int off = 16; off; off >>= 1)
            p += __shfl_xor_sync(0xffffffffu, p, off);
        s[c] = p;
    }
    if (lane == 0) {
        float dot = 0.f, ss = 0.f;
        #pragma unroll
        for (int c = 0; c < 3; c++) {
            float cm = s[c] * (1.f / 1024.f);
            dot += cm * g_aux[38 + c];
            ss  += cm * cm;
        }
        float v = dot / (sqrtf(25.f * ss) + EPSF) + 0.5f * g_aux[41] + c1[0];
        long long f = (long long)floorf(v / R_HASH);
        qh_out[b] = (int)(((f % 2) + 2) % 2);
    }
}

// ---------------------------------------------------------------------------
// Fused conv5x5(pad2)+bias+relu+mask+maxpool2 (R14 structure).
// Staging: zero-fill tile (float4 STS), then interior rows via float4 LDG.
// NOPREV=true: n_ci==CIN (identity channel map). FCOUT=true: pooled outputs
// go to smem, then per-sample FC epilogue writes the final [B,10] result.
// ---------------------------------------------------------------------------
template <int CIN, int COUT, int H, int W, int WPAD, int SPB, int T, int MINB,
          bool EPI, bool NOPREV, bool FCOUT>
__global__ __launch_bounds__(T, MINB)
void conv_fused(const float* __restrict__ in, float* __restrict__ out,
                const float* __restrict__ wpad, const float* __restrict__ bias,
                const int* __restrict__ kh, const int* __restrict__ qh,
                const int* __restrict__ kh_prev, const int* __restrict__ qh_prev,
                const float* __restrict__ asum_next,
                const float* __restrict__ tail_next,
                const float* __restrict__ c_next, int* __restrict__ qh_next,
                const float* __restrict__ Wo, const float* __restrict__ bo,
                float* __restrict__ fcout)
{
    constexpr int HP = H + 4;
    constexpr int PH = H / 2, PW = W / 2, PX2 = PW / 2;
    constexpr int PP = PH * PX2;
    constexpr int SEG = (PP < 32) ? PP : 32;
    constexpr int CHW = HP * WPAD;
    constexpr int WG = W / 4;                 // float4 groups per row
    constexpr int FCN = COUT * PH * PW;       // per-sample flattened size

    extern __shared__ float sm[];
    float* sx  = sm;
    float* scm = sx + SPB * CIN * CHW;
    float* sh3 = scm + SPB * COUT;            // FCOUT: SPB*FCN, else 0
    int* nact  = (int*)(sh3 + (FCOUT ? SPB * FCN : 0));
    int* soff  = nact + SPB;
    int* actco = soff + SPB + 1;
    int* nci   = actco + SPB * COUT;
    int* actci = nci + SPB;
    int* sxoff = actci + SPB * CIN;

    const int b0 = blockIdx.x * SPB;
    const int t  = threadIdx.x;

    if (t < SPB) {
        int s = t, n = 0, qv = qh[b0 + s];
        for (int co = 0; co < COUT; co++)
            if (kh[co] == qv) actco[s * COUT + n++] = co;
        nact[s] = n;
    } else if (t >= 32 && t < 32 + SPB) {
        int s = t - 32, n = 0;
        if (!NOPREV) {
            int qv = qh_prev[b0 + s];
            for (int c = 0; c < CIN; c++)
                if (kh_prev[c] == qv) actci[s * CIN + n++] = c;
        } else {
            for (int c = 0; c < CIN; c++) actci[s * CIN + n++] = c;
        }
        nci[s] = n;
    }
    if (EPI) for (int i = t; i < SPB * COUT; i += T) scm[i] = 0.f;
    if (FCOUT) for (int i = t; i < SPB * FCN; i += T) sh3[i] = 0.f;
    __syncthreads();
    if (t == 0) {
        int o = 0, xo = 0;
        for (int s = 0; s < SPB; s++) {
            soff[s] = o;  o  += nact[s] * PP;
            sxoff[s] = xo; xo += NOPREV ? CIN : nci[s];
        }
        soff[SPB] = o; sxoff[SPB] = xo;
    }
    __syncthreads();

    const int total_ch = sxoff[SPB];
    // zero-fill used portion of tile (float4 STS)
    {
        float4 z = make_float4(0.f, 0.f, 0.f, 0.f);
        float4* sx4 = (float4*)sx;
        const int n4 = total_ch * (CHW / 4);
        for (int i = t; i < n4; i += T) sx4[i] = z;
    }
    __syncthreads();
    // interior rows via float4 LDG + 4 scalar STS
    for (int i = t; i < total_ch * H * WG; i += T) {
        int xg = i % WG; int rest = i / WG;
        int y = rest % H; int ch = rest / H;
        int s = 0;
        #pragma unroll
        for (int ss = 0; ss < SPB - 1; ss++)
            if (ch >= sxoff[ss + 1]) s = ss + 1;
        int c = NOPREV ? (ch - sxoff[s]) : actci[s * CIN + (ch - sxoff[s])];
        float4 v = *(const float4*)(in + ((size_t)(b0 + s) * CIN + c) * (H * W)
                                    + y * W + 4 * xg);
        float* dst = sx + ch * CHW + (y + 2) * WPAD + 4 * xg + 2;
        dst[0] = v.x; dst[1] = v.y; dst[2] = v.z; dst[3] = v.w;
    }
    __syncthreads();
    const int total = soff[SPB];

    for (int item = t;; item += T) {
        if (!__ballot_sync(0xffffffffu, item < total)) break;
        float val = 0.f;
        int s = 0, co = 0;
        if (item < total) {
            #pragma unroll
            for (int ss = 0; ss < SPB - 1; ss++)
                if (item >= soff[ss + 1]) s = ss + 1;
            int local = item - soff[s];
            co = actco[s * COUT + local / PP];
            int rr = local % PP;
            int py = rr / PX2, px2 = rr % PX2;

            float acc[2][4] = {};
            const float* xb = sx + (size_t)sxoff[s] * CHW + (2 * py) * WPAD + 4 * px2;
            const int n_ci = NOPREV ? CIN : nci[s];
            const int* ci = actci + s * CIN;
            const float* wb_ = wpad + (size_t)co * CIN * 28;

            for (int j = 0; j < n_ci; j++) {
                int c = NOPREV ? j : ci[j];
                const float4* wr = (const float4*)(wb_ + c * 28);
                float4 q0 = __ldg(wr + 0), q1 = __ldg(wr + 1), q2 = __ldg(wr + 2);
                float4 q3 = __ldg(wr + 3), q4 = __ldg(wr + 4), q5 = __ldg(wr + 5);
                float4 q6 = __ldg(wr + 6);
                float w[25] = {q0.x, q0.y, q0.z, q0.w, q1.x, q1.y, q1.z, q1.w,
                               q2.x, q2.y, q2.z, q2.w, q3.x, q3.y, q3.z, q3.w,
                               q4.x, q4.y, q4.z, q4.w, q5.x, q5.y, q5.z, q5.w,
                               q6.x};
                const float* xs = xb + j * CHW;
                #pragma unroll
                for (int rw = 0; rw < 6; rw++) {
                    float4 x0 = *(const float4*)(xs + rw * WPAD);
                    float4 x1 = *(const float4*)(xs + rw * WPAD + 4);
                    float xr[8] = {x0.x, x0.y, x0.z, x0.w, x1.x, x1.y, x1.z, x1.w};
                    if (rw < 5) {
                        #pragma unroll
                        for (int kx = 0; kx < 5; kx++) {
                            float wa = w[rw * 5 + kx];
                            acc[0][0] += xr[kx + 0] * wa;
                            acc[0][1] += xr[kx + 1] * wa;
                            acc[0][2] += xr[kx + 2] * wa;
                            acc[0][3] += xr[kx + 3] * wa;
                        }
                    }
                    if (rw > 0) {
                        #pragma unroll
                        for (int kx = 0; kx < 5; kx++) {
                            float wb = w[(rw - 1) * 5 + kx];
                            acc[1][0] += xr[kx + 0] * wb;
                            acc[1][1] += xr[kx + 1] * wb;
                            acc[1][2] += xr[kx + 2] * wb;
                            acc[1][3] += xr[kx + 3] * wb;
                        }
                    }
                }
            }
            float bv = __ldg(bias + co);
            float v00 = fmaxf(acc[0][0] + bv, 0.f), v01 = fmaxf(acc[0][1] + bv, 0.f);
            float v02 = fmaxf(acc[0][2] + bv, 0.f), v03 = fmaxf(acc[0][3] + bv, 0.f);
            float v10 = fmaxf(acc[1][0] + bv, 0.f), v11 = fmaxf(acc[1][1] + bv, 0.f);
            float v12 = fmaxf(acc[1][2] + bv, 0.f), v13 = fmaxf(acc[1][3] + bv, 0.f);
            float o0 = fmaxf(fmaxf(v00, v01), fmaxf(v10, v11));
            float o1 = fmaxf(fmaxf(v02, v03), fmaxf(v12, v13));
            if (FCOUT) {
                float* hp = sh3 + s * FCN + (co * PH + py) * PW + px2 * 2;
                hp[0] = o0; hp[1] = o1;
            } else {
                float2* op = (float2*)&out[(((size_t)(b0 + s) * COUT + co) * PH + py) * PW + px2 * 2];
                *op = make_float2(o0, o1);
            }
            val = o0 + o1;
        }
        if (EPI) {
            #pragma unroll
            for (int off = SEG / 2; off; off >>= 1)
                val += __shfl_xor_sync(0xffffffffu, val, off);
            if ((t & (SEG - 1)) == 0 && item < total)
                atomicAdd(&scm[s * COUT + co], val);
        }
    }

    if (EPI) {
        __syncthreads();
        if (t < SPB) {
            int s = t;
            float dot = 0.f, ssum = 0.f;
            const float inv = 1.f / (float)(PH * PW);
            for (int c = 0; c < COUT; c++) {
                float cm = scm[s * COUT + c] * inv;
                dot  += cm * asum_next[c];
                ssum += cm * cm;
            }
            float v = dot / (sqrtf(25.f * ssum) + EPSF) + 0.5f * tail_next[0] + c_next[0];
            long long f = (long long)floorf(v / R_HASH);
            qh_next[b0 + s] = (int)(((f % 2) + 2) % 2);
        }
    }

    if (FCOUT) {
        __syncthreads();
        int w = t >> 5, lane = t & 31;
        if (w < SPB) {
            const float* hb = sh3 + w * FCN;
            float xv[10];
            #pragma unroll
            for (int j = 0; j < 10; j++) xv[j] = hb[lane + j * 32];
            #pragma unroll
            for (int o = 0; o < 10; o++) {
                float p = 0.f;
                #pragma unroll
                for (int j = 0; j < 10; j++)
                    p += xv[j] * __ldg(Wo + o * 320 + lane + j * 32);
                #pragma unroll
                for (int off = 16; off; off >>= 1)
                    p += __shfl_xor_sync(0xffffffffu, p, off);
                if (lane == 0)
                    fcout[(b0 + w) * 10 + o] = p + __ldg(bo + o);
            }
        }
    }
}

// ---------------------------------------------------------------------------
static inline int smem_bytes(int CIN, int COUT, int SPB, int HP, int WPAD, int fcn)
{
    int fl = SPB * CIN * HP * WPAD + SPB * COUT + SPB * fcn;
    int it = SPB + (SPB + 1) + SPB * COUT + SPB + SPB * CIN + (SPB + 1);
    return 4 * (fl + it);
}

extern "C" void kernel_launch(void* const* d_in, const int* in_sizes, int n_in,
                              void* d_out, int out_size)
{
    const float* x  = (const float*)d_in[0];
    const float* W1 = (const float*)d_in[1];
    const float* b1 = (const float*)d_in[2];
    const float* a1 = (const float*)d_in[3];
    const float* c1 = (const float*)d_in[4];
    const float* W2 = (const float*)d_in[5];
    const float* b2 = (const float*)d_in[6];
    const float* a2 = (const float*)d_in[7];
    const float* c2 = (const float*)d_in[8];
    const float* W3 = (const float*)d_in[9];
    const float* b3 = (const float*)d_in[10];
    const float* a3 = (const float*)d_in[11];
    const float* c3 = (const float*)d_in[12];
    const float* Wo = (const float*)d_in[13];
    const float* bo = (const float*)d_in[14];
    float* out = (float*)d_out;

    float *h1, *h2, *aux, *w1p, *w2p, *w3p; int *qh, *kh;
    cudaGetSymbolAddress((void**)&h1, g_h1);
    cudaGetSymbolAddress((void**)&h2, g_h2);
    cudaGetSymbolAddress((void**)&qh, g_qh);
    cudaGetSymbolAddress((void**)&kh, g_kh);
    cudaGetSymbolAddress((void**)&aux, g_aux);
    cudaGetSymbolAddress((void**)&w1p, g_w1p);
    cudaGetSymbolAddress((void**)&w2p, g_w2p);
    cudaGetSymbolAddress((void**)&w3p, g_w3p);

    const int sm1 = smem_bytes(3, 16, 1, 36, 36, 0);
    const int sm2 = smem_bytes(16, 20, 1, 20, 24, 0);
    const int sm3 = smem_bytes(20, 20, 2, 12, 12, 320);

    cudaFuncSetAttribute(
        (const void*)conv_fused<3, 16, 32, 32, 36, 1, 256, 4, true, true, false>,
        cudaFuncAttributeMaxDynamicSharedMemorySize, sm1);
    cudaFuncSetAttribute(
        (const void*)conv_fused<16, 20, 16, 16, 24, 1, 160, 6, true, false, false>,
        cudaFuncAttributeMaxDynamicSharedMemorySize, sm2);
    cudaFuncSetAttribute(
        (const void*)conv_fused<20, 20, 8, 8, 12, 2, 160, 6, false, false, true>,
        cudaFuncAttributeMaxDynamicSharedMemorySize, sm3);

    kh_all<<<8, 256>>>(W1, a1, c1, W2, a2, c2, W3, a3, c3);
    qh1_kernel<<<BATCH / 8, 256>>>(x, c1, qh);

    conv_fused<3, 16, 32, 32, 36, 1, 256, 4, true, true, false><<<BATCH, 256, sm1>>>(
        x, h1, w1p, b1, kh, qh, nullptr, nullptr,
        aux + 0, aux + 36, c2, qh + BATCH, nullptr, nullptr, nullptr);

    conv_fused<16, 20, 16, 16, 24, 1, 160, 6, true, false, false><<<BATCH, 160, sm2>>>(
        h1, h2, w2p, b2, kh + 32, qh + BATCH, kh, qh,
        aux + 16, aux + 37, c3, qh + 2 * BATCH, nullptr, nullptr, nullptr);

    conv_fused<20, 20, 8, 8, 12, 2, 160, 6, false, false, true><<<BATCH / 2, 160, sm3>>>(
        h2, nullptr, w3p, b3, kh + 64, qh + 2 * BATCH, kh + 32, qh + BATCH,
        nullptr, nullptr, nullptr, nullptr, Wo, bo, out);
}